// round 4
// baseline (speedup 1.0000x reference)
#include <cuda_runtime.h>

#define BSZ 32
#define LP 96
#define DM 12
#define ED 768
#define NS 8
#define NL 10
#define EMB 256
#define PP 50
#define ROWS (BSZ*LP)      // 3072
#define XZW (2*ED)         // 1536
#define DBLW 17            // DR + 2N

// ---------------- scratch (static device globals; no runtime alloc) ----------------
__device__ float g_h[ROWS*DM];        // residual stream
__device__ float g_xz[ROWS*XZW];      // in_proj output (xin | z)
__device__ float g_xc[ROWS*ED];       // conv+silu output
__device__ float g_dbl[ROWS*DBLW];    // x_proj output
__device__ float g_y[ROWS*ED];        // scan output (y * silu(z))
__device__ float g_A2[NL*ED*NS];      // -exp(A_log) * log2(e)

// ---------------- fast math helpers ----------------
__device__ __forceinline__ float ex2f_(float x){ float y; asm("ex2.approx.f32 %0, %1;":"=f"(y):"f"(x)); return y; }
__device__ __forceinline__ float lg2f_(float x){ float y; asm("lg2.approx.f32 %0, %1;":"=f"(y):"f"(x)); return y; }
__device__ __forceinline__ float rcpf_(float x){ float y; asm("rcp.approx.f32 %0, %1;":"=f"(y):"f"(x)); return y; }
#define L2E 1.4426950408889634f
#define LN2 0.6931471805599453f
__device__ __forceinline__ float sigmoidf_(float x){ return rcpf_(1.0f + ex2f_(-x*L2E)); }
__device__ __forceinline__ float siluf_(float x){ return x * sigmoidf_(x); }
__device__ __forceinline__ float softplusf_(float x){
    return (x > 20.0f) ? x : LN2*lg2f_(1.0f + ex2f_(x*L2E));
}

// ---------------- prep: A2 = -exp(A_log)*log2e ----------------
__global__ void k_prep(const float* __restrict__ A_log){
    int i = blockIdx.x*blockDim.x + threadIdx.x;
    if (i < NL*ED*NS) g_A2[i] = -expf(A_log[i]) * L2E;
}

// ---------------- front-end: complex projection + pos ----------------
__global__ void k_front(const float* __restrict__ x,
                        const float* __restrict__ rw, const float* __restrict__ rb,
                        const float* __restrict__ iw, const float* __restrict__ ib,
                        const float* __restrict__ pos){
    int idx = blockIdx.x*blockDim.x + threadIdx.x;
    if (idx >= ROWS*DM) return;
    int row = idx / DM, o = idx % DM;
    int b = row / LP, l = row % LP;
    const float* xr = x + b*(2*LP*PP) + l*PP;
    const float* xi = xr + LP*PP;
    float acc;
    if (o < 6){
        acc = rb[o] - ib[o];
        const float* w1 = rw + o*PP; const float* w2 = iw + o*PP;
        #pragma unroll 10
        for (int k=0;k<PP;k++) acc += xr[k]*w1[k] - xi[k]*w2[k];
    } else {
        int o6 = o-6;
        acc = rb[o6] + ib[o6];
        const float* w1 = rw + o6*PP; const float* w2 = iw + o6*PP;
        #pragma unroll 10
        for (int k=0;k<PP;k++) acc += xi[k]*w1[k] + xr[k]*w2[k];
    }
    g_h[idx] = acc + pos[l*DM + o];
}

// ---------------- batchnorm (over all rows, per channel) + silu ----------------
__global__ void k_bn(const float* __restrict__ gamma, const float* __restrict__ beta){
    __shared__ float s_sum[DM], s_sq[DM], s_scale[DM], s_shift[DM];
    int tid = threadIdx.x;
    if (tid < DM){ s_sum[tid]=0.f; s_sq[tid]=0.f; }
    __syncthreads();
    float ls[DM], lq[DM];
    #pragma unroll
    for(int c=0;c<DM;c++){ ls[c]=0.f; lq[c]=0.f; }
    for (int j=tid;j<ROWS;j+=blockDim.x){
        #pragma unroll
        for(int c=0;c<DM;c++){ float v=g_h[j*DM+c]; ls[c]+=v; lq[c]+=v*v; }
    }
    #pragma unroll
    for(int c=0;c<DM;c++){
        float a=ls[c], q=lq[c];
        for(int off=16;off>0;off>>=1){
            a+=__shfl_down_sync(0xffffffffu,a,off);
            q+=__shfl_down_sync(0xffffffffu,q,off);
        }
        if((tid&31)==0){ atomicAdd(&s_sum[c],a); atomicAdd(&s_sq[c],q); }
    }
    __syncthreads();
    if (tid < DM){
        float mu  = s_sum[tid]*(1.0f/ROWS);
        float var = s_sq[tid]*(1.0f/ROWS) - mu*mu;
        float sc  = rsqrtf(var+1e-6f)*gamma[tid];
        s_scale[tid]=sc; s_shift[tid]=beta[tid]-mu*sc;
    }
    __syncthreads();
    for (int j=tid;j<ROWS;j+=blockDim.x){
        #pragma unroll
        for(int c=0;c<DM;c++){
            float v = g_h[j*DM+c]*s_scale[c]+s_shift[c];
            g_h[j*DM+c] = siluf_(v);
        }
    }
}

// ---------------- rmsnorm + in_proj: 32 rows/block, weights in registers ----------------
__global__ void __launch_bounds__(256) k_inproj(const float* __restrict__ rmsw,
                                                const float* __restrict__ W, int layer){
    __shared__ float su[32][DM];
    __shared__ float srms[32];
    int r0 = blockIdx.x*32;
    int tid = threadIdx.x;
    const float* Wl  = W + layer*XZW*DM;
    const float* rwl = rmsw + layer*DM;
    for (int t=tid; t<32*DM; t+=256) su[t/DM][t%DM] = g_h[r0*DM + t];
    __syncthreads();
    if (tid < 32){
        float s=0.f;
        #pragma unroll
        for(int d=0;d<DM;d++){ float v=su[tid][d]; s+=v*v; }
        srms[tid] = rsqrtf(s*(1.0f/DM)+1e-5f);
    }
    __syncthreads();
    for (int t=tid; t<32*DM; t+=256){
        int r=t/DM, d=t%DM;
        su[r][d] = su[r][d]*srms[r]*rwl[d];
    }
    __syncthreads();
    // each thread owns 6 output columns o = tid + 256*j (coalesced stores)
    float w[6][DM];
    #pragma unroll
    for(int j=0;j<6;j++){
        const float* wp = Wl + (tid + 256*j)*DM;
        #pragma unroll
        for(int d=0;d<DM;d++) w[j][d]=wp[d];
    }
    for (int r=0;r<32;r++){
        float u[DM];
        #pragma unroll
        for(int d=0;d<DM;d++) u[d]=su[r][d];
        #pragma unroll
        for(int j=0;j<6;j++){
            float acc=0.f;
            #pragma unroll
            for(int d=0;d<DM;d++) acc += u[d]*w[j][d];
            g_xz[(r0+r)*XZW + tid + 256*j] = acc;
        }
    }
}

// ---------------- causal conv (width 3) + silu ----------------
__global__ void k_conv(const float* __restrict__ cw, const float* __restrict__ cb, int layer){
    int idx = blockIdx.x*blockDim.x + threadIdx.x;
    if (idx >= ROWS*ED) return;
    int row = idx / ED, e = idx % ED;
    int l = row % LP;
    const float* wp = cw + (layer*ED + e)*3;
    float acc = cb[layer*ED + e];
    acc += wp[2] * g_xz[row*XZW + e];
    if (l >= 1) acc += wp[1] * g_xz[(row-1)*XZW + e];
    if (l >= 2) acc += wp[0] * g_xz[(row-2)*XZW + e];
    g_xc[idx] = siluf_(acc);
}

// ---------------- x_proj: warp per row, 17 partials ----------------
__global__ void __launch_bounds__(256) k_xproj(const float* __restrict__ W, int layer){
    int warp = threadIdx.x >> 5, lane = threadIdx.x & 31;
    int row = blockIdx.x*8 + warp;
    const float* Wl = W + layer*DBLW*ED;
    float part[DBLW];
    #pragma unroll
    for(int r=0;r<DBLW;r++) part[r]=0.f;
    for (int e=lane; e<ED; e+=32){
        float xv = g_xc[row*ED + e];
        #pragma unroll
        for(int r=0;r<DBLW;r++) part[r] += xv * Wl[r*ED + e];
    }
    #pragma unroll
    for(int r=0;r<DBLW;r++){
        float v = part[r];
        for(int off=16;off>0;off>>=1) v += __shfl_down_sync(0xffffffffu, v, off);
        if (lane==0) g_dbl[row*DBLW + r] = v;
    }
}

// ---------------- selective scan: thread per (b,e), states in registers ----------------
__global__ void __launch_bounds__(128) k_scan(const float* __restrict__ dtw,
                                              const float* __restrict__ dtb,
                                              const float* __restrict__ Dp, int layer){
    __shared__ float sdbl[LP*DBLW];   // 96*17 = 1632 floats
    int b = blockIdx.x / (ED/128);
    int e = (blockIdx.x % (ED/128))*128 + threadIdx.x;
    for (int t=threadIdx.x; t<LP*DBLW; t+=128) sdbl[t] = g_dbl[(b*LP)*DBLW + t];
    __syncthreads();
    float a2[NS];
    const float* ap = g_A2 + (layer*ED + e)*NS;
    #pragma unroll
    for(int n=0;n<NS;n++) a2[n]=ap[n];
    float dw = dtw[layer*ED + e];
    float db = dtb[layer*ED + e];
    float Dv = Dp [layer*ED + e];
    float st[NS];
    #pragma unroll
    for(int n=0;n<NS;n++) st[n]=0.f;
    int rowbase = b*LP;
    for (int l=0;l<LP;l++){
        int row = rowbase + l;
        float xc = g_xc[row*ED + e];
        float z  = g_xz[row*XZW + ED + e];
        const float* dl = sdbl + l*DBLW;
        float delta = softplusf_(dl[0]*dw + db);
        float dx = delta * xc;
        float y  = Dv * xc;
        #pragma unroll
        for(int n=0;n<NS;n++){
            float da = ex2f_(delta * a2[n]);
            st[n] = da*st[n] + dx*dl[1+n];
            y += st[n]*dl[9+n];
        }
        g_y[row*ED + e] = y * siluf_(z);
    }
}

// ---------------- out_proj: warp per row, accumulate into residual ----------------
__global__ void __launch_bounds__(256) k_outproj(const float* __restrict__ W, int layer){
    int warp = threadIdx.x >> 5, lane = threadIdx.x & 31;
    int row = blockIdx.x*8 + warp;
    const float* Wl = W + layer*DM*ED;
    float part[DM];
    #pragma unroll
    for(int d=0;d<DM;d++) part[d]=0.f;
    for (int e=lane;e<ED;e+=32){
        float yv = g_y[row*ED+e];
        #pragma unroll
        for(int d=0;d<DM;d++) part[d] += yv*Wl[d*ED+e];
    }
    #pragma unroll
    for(int d=0;d<DM;d++){
        float v=part[d];
        for(int off=16;off>0;off>>=1) v+=__shfl_down_sync(0xffffffffu,v,off);
        if(lane==0) g_h[row*DM+d]+=v;
    }
}

// ---------------- final: mean over L + FC + ReLU ----------------
__global__ void k_final(const float* __restrict__ fcw, const float* __restrict__ fcb,
                        float* __restrict__ out){
    __shared__ float m[DM];
    int b = blockIdx.x, tid = threadIdx.x;
    if (tid < DM){
        float s=0.f;
        for(int l=0;l<LP;l++) s += g_h[(b*LP+l)*DM + tid];
        m[tid]=s*(1.0f/LP);
    }
    __syncthreads();
    float acc = fcb[tid];
    #pragma unroll
    for(int d=0;d<DM;d++) acc += m[d]*fcw[tid*DM+d];
    out[b*EMB+tid] = fmaxf(acc,0.0f);
}

// ---------------- launch ----------------
extern "C" void kernel_launch(void* const* d_in, const int* in_sizes, int n_in,
                              void* d_out, int out_size){
    const float* x          = (const float*)d_in[0];
    const float* conv_re_w  = (const float*)d_in[1];
    const float* conv_re_b  = (const float*)d_in[2];
    const float* conv_im_w  = (const float*)d_in[3];
    const float* conv_im_b  = (const float*)d_in[4];
    const float* pos        = (const float*)d_in[5];
    const float* bn_gamma   = (const float*)d_in[6];
    const float* bn_beta    = (const float*)d_in[7];
    const float* rms_w      = (const float*)d_in[8];
    const float* in_proj_w  = (const float*)d_in[9];
    const float* conv1d_w   = (const float*)d_in[10];
    const float* conv1d_b   = (const float*)d_in[11];
    const float* x_proj_w   = (const float*)d_in[12];
    const float* dt_proj_w  = (const float*)d_in[13];
    const float* dt_proj_b  = (const float*)d_in[14];
    const float* A_log      = (const float*)d_in[15];
    const float* Dp         = (const float*)d_in[16];
    const float* out_proj_w = (const float*)d_in[17];
    const float* fc_w       = (const float*)d_in[18];
    const float* fc_b       = (const float*)d_in[19];
    float* out = (float*)d_out;

    k_prep <<<(NL*ED*NS+255)/256,256>>>(A_log);
    k_front<<<(ROWS*DM+255)/256,256>>>(x, conv_re_w, conv_re_b, conv_im_w, conv_im_b, pos);
    k_bn   <<<1,512>>>(bn_gamma, bn_beta);
    for (int i=0;i<NL;i++){
        k_inproj <<<ROWS/32,      256>>>(rms_w, in_proj_w, i);
        k_conv   <<<ROWS*ED/256,  256>>>(conv1d_w, conv1d_b, i);
        k_xproj  <<<ROWS/8,       256>>>(x_proj_w, i);
        k_scan   <<<BSZ*(ED/128), 128>>>(dt_proj_w, dt_proj_b, Dp, i);
        k_outproj<<<ROWS/8,       256>>>(out_proj_w, i);
    }
    k_final<<<BSZ,EMB>>>(fc_w, fc_b, out);
}

// round 5
// speedup vs baseline: 1.2371x; 1.2371x over previous
#include <cuda_runtime.h>

#define BSZ 32
#define LP 96
#define DM 12
#define ED 768
#define NS 8
#define NL 10
#define EMB 256
#define PP 50
#define ROWS (BSZ*LP)      // 3072
#define XZW (2*ED)         // 1536
#define DBLW 17            // DR + 2N

// ---------------- scratch ----------------
__device__ float g_h[ROWS*DM];        // residual stream
__device__ float g_xz[ROWS*XZW];      // in_proj output (xin | silu(z) after convxproj)
__device__ float g_xc[ROWS*ED];       // conv+silu output
__device__ float g_dbl[ROWS*DBLW];    // x_proj output
__device__ float g_A2[NL*ED*NS];      // -exp(A_log) * log2(e)

// ---------------- fast math ----------------
__device__ __forceinline__ float ex2f_(float x){ float y; asm("ex2.approx.f32 %0, %1;":"=f"(y):"f"(x)); return y; }
__device__ __forceinline__ float lg2f_(float x){ float y; asm("lg2.approx.f32 %0, %1;":"=f"(y):"f"(x)); return y; }
__device__ __forceinline__ float rcpf_(float x){ float y; asm("rcp.approx.f32 %0, %1;":"=f"(y):"f"(x)); return y; }
#define L2E 1.4426950408889634f
#define LN2 0.6931471805599453f
__device__ __forceinline__ float sigmoidf_(float x){ return rcpf_(1.0f + ex2f_(-x*L2E)); }
__device__ __forceinline__ float siluf_(float x){ return x * sigmoidf_(x); }
__device__ __forceinline__ float softplusf_(float x){
    return (x > 20.0f) ? x : LN2*lg2f_(1.0f + ex2f_(x*L2E));
}

// ---------------- prep ----------------
__global__ void k_prep(const float* __restrict__ A_log){
    int i = blockIdx.x*blockDim.x + threadIdx.x;
    if (i < NL*ED*NS) g_A2[i] = -expf(A_log[i]) * L2E;
}

// ---------------- front-end: complex projection + pos ----------------
__global__ void k_front(const float* __restrict__ x,
                        const float* __restrict__ rw, const float* __restrict__ rb,
                        const float* __restrict__ iw, const float* __restrict__ ib,
                        const float* __restrict__ pos){
    int idx = blockIdx.x*blockDim.x + threadIdx.x;
    if (idx >= ROWS*DM) return;
    int row = idx / DM, o = idx % DM;
    int b = row / LP, l = row % LP;
    const float* xr = x + b*(2*LP*PP) + l*PP;
    const float* xi = xr + LP*PP;
    float acc;
    if (o < 6){
        acc = rb[o] - ib[o];
        const float* w1 = rw + o*PP; const float* w2 = iw + o*PP;
        #pragma unroll 10
        for (int k=0;k<PP;k++) acc += xr[k]*w1[k] - xi[k]*w2[k];
    } else {
        int o6 = o-6;
        acc = rb[o6] + ib[o6];
        const float* w1 = rw + o6*PP; const float* w2 = iw + o6*PP;
        #pragma unroll 10
        for (int k=0;k<PP;k++) acc += xi[k]*w1[k] + xr[k]*w2[k];
    }
    g_h[idx] = acc + pos[l*DM + o];
}

// ---------------- batchnorm over all rows + silu ----------------
__global__ void k_bn(const float* __restrict__ gamma, const float* __restrict__ beta){
    __shared__ float s_sum[DM], s_sq[DM], s_scale[DM], s_shift[DM];
    int tid = threadIdx.x;
    if (tid < DM){ s_sum[tid]=0.f; s_sq[tid]=0.f; }
    __syncthreads();
    float ls[DM], lq[DM];
    #pragma unroll
    for(int c=0;c<DM;c++){ ls[c]=0.f; lq[c]=0.f; }
    for (int j=tid;j<ROWS;j+=blockDim.x){
        #pragma unroll
        for(int c=0;c<DM;c++){ float v=g_h[j*DM+c]; ls[c]+=v; lq[c]+=v*v; }
    }
    #pragma unroll
    for(int c=0;c<DM;c++){
        float a=ls[c], q=lq[c];
        for(int off=16;off>0;off>>=1){
            a+=__shfl_down_sync(0xffffffffu,a,off);
            q+=__shfl_down_sync(0xffffffffu,q,off);
        }
        if((tid&31)==0){ atomicAdd(&s_sum[c],a); atomicAdd(&s_sq[c],q); }
    }
    __syncthreads();
    if (tid < DM){
        float mu  = s_sum[tid]*(1.0f/ROWS);
        float var = s_sq[tid]*(1.0f/ROWS) - mu*mu;
        float sc  = rsqrtf(var+1e-6f)*gamma[tid];
        s_scale[tid]=sc; s_shift[tid]=beta[tid]-mu*sc;
    }
    __syncthreads();
    for (int j=tid;j<ROWS;j+=blockDim.x){
        #pragma unroll
        for(int c=0;c<DM;c++){
            float v = g_h[j*DM+c]*s_scale[c]+s_shift[c];
            g_h[j*DM+c] = siluf_(v);
        }
    }
}

// ---------------- rmsnorm + in_proj: 148 blocks, ~21 rows each ----------------
__global__ void __launch_bounds__(256) k_inproj(const float* __restrict__ rmsw,
                                                const float* __restrict__ W, int layer){
    __shared__ float su[21*DM];
    __shared__ float srms[21];
    int bid = blockIdx.x;
    int r0 = bid*20 + (bid < 112 ? bid : 112);
    int nr = 20 + (bid < 112 ? 1 : 0);
    int tid = threadIdx.x;
    const float* Wl  = W + layer*XZW*DM;
    const float* rwl = rmsw + layer*DM;
    for (int t=tid; t<nr*DM; t+=256) su[t] = g_h[r0*DM + t];
    __syncthreads();
    if (tid < nr){
        float s=0.f;
        #pragma unroll
        for(int d=0;d<DM;d++){ float v=su[tid*DM+d]; s+=v*v; }
        srms[tid] = rsqrtf(s*(1.0f/DM)+1e-5f);
    }
    __syncthreads();
    for (int t=tid; t<nr*DM; t+=256) su[t] = su[t]*srms[t/DM]*rwl[t%DM];
    __syncthreads();
    // each thread owns 6 output columns o = tid + 256*j
    float w[6][DM];
    #pragma unroll
    for(int j=0;j<6;j++){
        const float* wp = Wl + (tid + 256*j)*DM;
        #pragma unroll
        for(int d=0;d<DM;d++) w[j][d]=wp[d];
    }
    for (int r=0;r<nr;r++){
        float u[DM];
        #pragma unroll
        for(int d=0;d<DM;d++) u[d]=su[r*DM+d];
        #pragma unroll
        for(int j=0;j<6;j++){
            float acc=0.f;
            #pragma unroll
            for(int d=0;d<DM;d++) acc += u[d]*w[j][d];
            g_xz[(r0+r)*XZW + tid + 256*j] = acc;
        }
    }
}

// ---------------- fused conv(3)+silu + silu(z) + x_proj: 4 rows/warp ----------------
// grid 128 x 192 threads (6 warps x 4 rows = 24 rows/block)
__global__ void __launch_bounds__(192) k_cvxp(const float* __restrict__ cw,
                                              const float* __restrict__ cb,
                                              const float* __restrict__ W, int layer){
    int warp = threadIdx.x >> 5, lane = threadIdx.x & 31;
    int rbase = blockIdx.x*24 + warp*4;     // 4 | 96 so rows rbase..rbase+3 share a batch
    int l0 = rbase % LP;
    const float* Wl = W + layer*DBLW*ED;
    float part[4][DBLW];
    #pragma unroll
    for(int r=0;r<4;r++)
        #pragma unroll
        for(int t=0;t<DBLW;t++) part[r][t]=0.f;

    for (int k=0;k<ED/32;k++){
        int e = k*32 + lane;
        const float* wp = cw + (layer*ED + e)*3;
        float w0=wp[0], w1=wp[1], w2=wp[2];
        float bias = cb[layer*ED + e];
        // xin values rows rbase-2 .. rbase+3
        float xv[6];
        xv[0] = (l0>=2) ? g_xz[(rbase-2)*XZW + e] : 0.f;
        xv[1] = (l0>=1) ? g_xz[(rbase-1)*XZW + e] : 0.f;
        #pragma unroll
        for(int r=0;r<4;r++) xv[2+r] = g_xz[(rbase+r)*XZW + e];
        float xc[4];
        #pragma unroll
        for(int r=0;r<4;r++){
            float a = bias + w0*xv[r] + w1*xv[r+1] + w2*xv[r+2];
            xc[r] = siluf_(a);
            g_xc[(rbase+r)*ED + e] = xc[r];
            // gate: overwrite z with silu(z)
            float zv = g_xz[(rbase+r)*XZW + ED + e];
            g_xz[(rbase+r)*XZW + ED + e] = siluf_(zv);
        }
        #pragma unroll
        for(int t=0;t<DBLW;t++){
            float wv = __ldg(Wl + t*ED + e);
            #pragma unroll
            for(int r=0;r<4;r++) part[r][t] += xc[r]*wv;
        }
    }
    #pragma unroll
    for(int r=0;r<4;r++){
        #pragma unroll
        for(int t=0;t<DBLW;t++){
            float v = part[r][t];
            for(int off=16;off>0;off>>=1) v += __shfl_down_sync(0xffffffffu, v, off);
            if (lane==0) g_dbl[(rbase+r)*DBLW + t] = v;
        }
    }
}

// ---------------- fused scan + gate + out_proj ----------------
// grid = 32 batches x 4 e-chunks = 128 blocks, 192 threads (chunk = 192 e's)
__global__ void __launch_bounds__(192) k_scan(const float* __restrict__ dtw,
                                              const float* __restrict__ dtb,
                                              const float* __restrict__ Dp,
                                              const float* __restrict__ Wout, int layer){
    __shared__ float sdbl[LP*DBLW];     // 6528 B
    __shared__ float sy[48*192];        // 36864 B (two phases of 48 rows)
    int b  = blockIdx.x >> 2;
    int ch = blockIdx.x & 3;
    int tid = threadIdx.x, warp = tid>>5, lane = tid&31;
    int e = ch*192 + tid;
    for (int t=tid; t<LP*DBLW; t+=192) sdbl[t] = g_dbl[(b*LP)*DBLW + t];

    float a2[NS];
    const float* ap = g_A2 + (layer*ED + e)*NS;
    #pragma unroll
    for(int n=0;n<NS;n++) a2[n]=ap[n];
    bool geo = true;
    #pragma unroll
    for(int n=1;n<NS;n++)
        geo = geo && (fabsf(a2[n] - (float)(n+1)*a2[0]) <= 1e-4f*fabsf(a2[n]));
    float dw = dtw[layer*ED + e];
    float db = dtb[layer*ED + e];
    float Dv = Dp [layer*ED + e];
    // out_proj weight slice for this thread's lane columns (e = ch*192 + lane + 32*j)
    float wd[DM][6];
    #pragma unroll
    for(int d=0;d<DM;d++){
        const float* wp = Wout + (layer*DM + d)*ED + ch*192 + lane;
        #pragma unroll
        for(int j=0;j<6;j++) wd[d][j] = wp[32*j];
    }
    float st[NS];
    #pragma unroll
    for(int n=0;n<NS;n++) st[n]=0.f;
    int rowbase = b*LP;
    __syncthreads();

    float xc_n = g_xc[rowbase*ED + e];
    float sz_n = g_xz[rowbase*XZW + ED + e];

    for (int ph=0; ph<2; ph++){
        int lbeg = ph*48;
        for (int li=0; li<48; li++){
            int l = lbeg + li;
            float xc = xc_n, sz = sz_n;
            int ln = (l<LP-1) ? l+1 : l;
            xc_n = g_xc[(rowbase+ln)*ED + e];
            sz_n = g_xz[(rowbase+ln)*XZW + ED + e];
            const float* dl = sdbl + l*DBLW;
            float delta = softplusf_(dl[0]*dw + db);
            float dx = delta * xc;
            float y  = Dv * xc;
            float da[NS];
            if (geo){
                float p = ex2f_(delta * a2[0]);
                da[0] = p;
                #pragma unroll
                for(int n=1;n<NS;n++) da[n] = da[n-1]*p;
            } else {
                #pragma unroll
                for(int n=0;n<NS;n++) da[n] = ex2f_(delta * a2[n]);
            }
            #pragma unroll
            for(int n=0;n<NS;n++){
                st[n] = da[n]*st[n] + dx*dl[1+n];
                y += st[n]*dl[9+n];
            }
            sy[li*192 + tid] = y * sz;
        }
        __syncthreads();
        // partial out_proj over this chunk's 192 e's, rows lbeg..lbeg+47
        for (int kk=0; kk<8; kk++){
            int li = warp + 6*kk;   // 6 warps x 8 = 48 rows
            float prt[DM];
            #pragma unroll
            for(int d=0;d<DM;d++) prt[d]=0.f;
            #pragma unroll
            for(int j=0;j<6;j++){
                float yv = sy[li*192 + lane + 32*j];
                #pragma unroll
                for(int d=0;d<DM;d++) prt[d] += yv*wd[d][j];
            }
            #pragma unroll
            for(int d=0;d<DM;d++){
                float v = prt[d];
                for(int off=16;off>0;off>>=1) v += __shfl_down_sync(0xffffffffu, v, off);
                if (lane==0) atomicAdd(&g_h[(rowbase+lbeg+li)*DM + d], v);
            }
        }
        __syncthreads();
    }
}

// ---------------- final: mean over L + FC + ReLU ----------------
__global__ void k_final(const float* __restrict__ fcw, const float* __restrict__ fcb,
                        float* __restrict__ out){
    __shared__ float m[DM];
    int b = blockIdx.x, tid = threadIdx.x;
    if (tid < DM){
        float s=0.f;
        for(int l=0;l<LP;l++) s += g_h[(b*LP+l)*DM + tid];
        m[tid]=s*(1.0f/LP);
    }
    __syncthreads();
    float acc = fcb[tid];
    #pragma unroll
    for(int d=0;d<DM;d++) acc += m[d]*fcw[tid*DM+d];
    out[b*EMB+tid] = fmaxf(acc,0.0f);
}

// ---------------- launch ----------------
extern "C" void kernel_launch(void* const* d_in, const int* in_sizes, int n_in,
                              void* d_out, int out_size){
    const float* x          = (const float*)d_in[0];
    const float* conv_re_w  = (const float*)d_in[1];
    const float* conv_re_b  = (const float*)d_in[2];
    const float* conv_im_w  = (const float*)d_in[3];
    const float* conv_im_b  = (const float*)d_in[4];
    const float* pos        = (const float*)d_in[5];
    const float* bn_gamma   = (const float*)d_in[6];
    const float* bn_beta    = (const float*)d_in[7];
    const float* rms_w      = (const float*)d_in[8];
    const float* in_proj_w  = (const float*)d_in[9];
    const float* conv1d_w   = (const float*)d_in[10];
    const float* conv1d_b   = (const float*)d_in[11];
    const float* x_proj_w   = (const float*)d_in[12];
    const float* dt_proj_w  = (const float*)d_in[13];
    const float* dt_proj_b  = (const float*)d_in[14];
    const float* A_log      = (const float*)d_in[15];
    const float* Dp         = (const float*)d_in[16];
    const float* out_proj_w = (const float*)d_in[17];
    const float* fc_w       = (const float*)d_in[18];
    const float* fc_b       = (const float*)d_in[19];
    float* out = (float*)d_out;

    k_prep <<<(NL*ED*NS+255)/256,256>>>(A_log);
    k_front<<<(ROWS*DM+255)/256,256>>>(x, conv_re_w, conv_re_b, conv_im_w, conv_im_b, pos);
    k_bn   <<<1,1024>>>(bn_gamma, bn_beta);
    for (int i=0;i<NL;i++){
        k_inproj<<<148,256>>>(rms_w, in_proj_w, i);
        k_cvxp  <<<128,192>>>(conv1d_w, conv1d_b, x_proj_w, i);
        k_scan  <<<128,192>>>(dt_proj_w, dt_proj_b, Dp, out_proj_w, i);
    }
    k_final<<<BSZ,EMB>>>(fc_w, fc_b, out);
}

// round 6
// speedup vs baseline: 1.2372x; 1.0001x over previous
#include <cuda_runtime.h>

#define BSZ 32
#define LP 96
#define DM 12
#define ED 768
#define NS 8
#define NL 10
#define EMB 256
#define PP 50
#define ROWS (BSZ*LP)      // 3072
#define XZW (2*ED)         // 1536
#define DBLW 17            // DR + 2N

// ---------------- scratch ----------------
__device__ float g_h[ROWS*DM];
__device__ float g_xz[ROWS*XZW];
__device__ float g_xc[ROWS*ED];
__device__ float g_dbl[ROWS*DBLW];
__device__ float g_A2[NL*ED*NS];
__device__ float g_bns[2*DM];
__device__ volatile unsigned g_bar_gen;
__device__ unsigned g_bar_cnt;

// ---------------- fast math ----------------
__device__ __forceinline__ float ex2f_(float x){ float y; asm("ex2.approx.f32 %0, %1;":"=f"(y):"f"(x)); return y; }
__device__ __forceinline__ float lg2f_(float x){ float y; asm("lg2.approx.f32 %0, %1;":"=f"(y):"f"(x)); return y; }
__device__ __forceinline__ float rcpf_(float x){ float y; asm("rcp.approx.f32 %0, %1;":"=f"(y):"f"(x)); return y; }
#define L2E 1.4426950408889634f
#define LN2 0.6931471805599453f
__device__ __forceinline__ float sigmoidf_(float x){ return rcpf_(1.0f + ex2f_(-x*L2E)); }
__device__ __forceinline__ float siluf_(float x){ return x * sigmoidf_(x); }
__device__ __forceinline__ float softplusf_(float x){
    return (x > 20.0f) ? x : LN2*lg2f_(1.0f + ex2f_(x*L2E));
}

// ---------------- grid barrier (all blocks co-resident: grid == #SMs) ----------------
__device__ __forceinline__ void gridbar(){
    __syncthreads();
    if (threadIdx.x == 0){
        __threadfence();
        unsigned gen = g_bar_gen;
        unsigned old = atomicAdd(&g_bar_cnt, 1u);
        if (old == gridDim.x - 1u){
            g_bar_cnt = 0u;
            __threadfence();
            g_bar_gen = gen + 1u;
        } else {
            while (g_bar_gen == gen) __nanosleep(20);
        }
        __threadfence();
    }
    __syncthreads();
}

// ---------------- the megakernel ----------------
__global__ void __launch_bounds__(256) k_mega(
    const float* __restrict__ x,
    const float* __restrict__ conv_re_w, const float* __restrict__ conv_re_b,
    const float* __restrict__ conv_im_w, const float* __restrict__ conv_im_b,
    const float* __restrict__ pos,
    const float* __restrict__ bn_gamma, const float* __restrict__ bn_beta,
    const float* __restrict__ rms_w,
    const float* __restrict__ in_proj_w,
    const float* __restrict__ conv1d_w, const float* __restrict__ conv1d_b,
    const float* __restrict__ x_proj_w,
    const float* __restrict__ dt_proj_w, const float* __restrict__ dt_proj_b,
    const float* __restrict__ A_log,  const float* __restrict__ Dp,
    const float* __restrict__ out_proj_w,
    const float* __restrict__ fc_w, const float* __restrict__ fc_b,
    float* __restrict__ out)
{
    __shared__ float sbuf[LP*DBLW + 48*192];   // 43392 B, reused per phase
    const int NB  = gridDim.x;
    const int bid = blockIdx.x;
    const int tid = threadIdx.x;
    const int gsz = NB*256;
    const int gtid = bid*256 + tid;
    const int warp = tid >> 5, lane = tid & 31;

    // ===== phase 0: A2 prep + front-end + zero BN accumulators =====
    for (int i = gtid; i < NL*ED*NS; i += gsz) g_A2[i] = -expf(A_log[i]) * L2E;
    if (gtid < 2*DM) g_bns[gtid] = 0.f;
    for (int idx = gtid; idx < ROWS*DM; idx += gsz){
        int row = idx / DM, o = idx % DM;
        int b = row / LP, l = row % LP;
        const float* xr = x + b*(2*LP*PP) + l*PP;
        const float* xi = xr + LP*PP;
        float acc;
        if (o < 6){
            acc = conv_re_b[o] - conv_im_b[o];
            const float* w1 = conv_re_w + o*PP; const float* w2 = conv_im_w + o*PP;
            #pragma unroll 10
            for (int k=0;k<PP;k++) acc += xr[k]*w1[k] - xi[k]*w2[k];
        } else {
            int o6 = o-6;
            acc = conv_re_b[o6] + conv_im_b[o6];
            const float* w1 = conv_re_w + o6*PP; const float* w2 = conv_im_w + o6*PP;
            #pragma unroll 10
            for (int k=0;k<PP;k++) acc += xi[k]*w1[k] + xr[k]*w2[k];
        }
        g_h[idx] = acc + pos[l*DM + o];
    }
    gridbar();

    // ===== BN: global sums =====
    {
        float ls[DM], lq[DM];
        #pragma unroll
        for(int c=0;c<DM;c++){ ls[c]=0.f; lq[c]=0.f; }
        for (int j = gtid; j < ROWS; j += gsz){
            #pragma unroll
            for(int c=0;c<DM;c++){ float v=g_h[j*DM+c]; ls[c]+=v; lq[c]+=v*v; }
        }
        #pragma unroll
        for(int c=0;c<DM;c++){
            float a=ls[c], q=lq[c];
            for(int off=16;off>0;off>>=1){
                a+=__shfl_down_sync(0xffffffffu,a,off);
                q+=__shfl_down_sync(0xffffffffu,q,off);
            }
            if (lane==0 && (a!=0.f || q!=0.f)){
                atomicAdd(&g_bns[c], a);
                atomicAdd(&g_bns[DM+c], q);
            }
        }
    }
    gridbar();

    // ===== BN: apply + silu =====
    {
        if (tid < DM){
            float mu  = g_bns[tid]*(1.0f/ROWS);
            float var = g_bns[DM+tid]*(1.0f/ROWS) - mu*mu;
            float sc  = rsqrtf(var+1e-6f)*bn_gamma[tid];
            sbuf[tid]     = sc;
            sbuf[DM+tid]  = bn_beta[tid] - mu*sc;
        }
        __syncthreads();
        for (int idx = gtid; idx < ROWS*DM; idx += gsz){
            int c = idx % DM;
            float v = g_h[idx]*sbuf[c] + sbuf[DM+c];
            g_h[idx] = siluf_(v);
        }
    }
    gridbar();

    // ===== layers =====
    for (int layer = 0; layer < NL; layer++){
        // ---- rmsnorm + in_proj ----
        {
            float* su   = sbuf;            // up to 48 rows * DM
            float* srms = sbuf + 48*DM;
            int rb = (ROWS + NB - 1)/NB;   // <=48 for NB>=64
            int r0 = bid*rb;
            int nr = ROWS - r0; if (nr > rb) nr = rb;
            if (nr > 0){
                const float* Wl  = in_proj_w + layer*XZW*DM;
                const float* rwl = rms_w + layer*DM;
                for (int t=tid; t<nr*DM; t+=256) su[t] = g_h[r0*DM + t];
                __syncthreads();
                if (tid < nr){
                    float s=0.f;
                    #pragma unroll
                    for(int d=0;d<DM;d++){ float v=su[tid*DM+d]; s+=v*v; }
                    srms[tid] = rsqrtf(s*(1.0f/DM)+1e-5f);
                }
                __syncthreads();
                for (int t=tid; t<nr*DM; t+=256) su[t] = su[t]*srms[t/DM]*rwl[t%DM];
                __syncthreads();
                float w[6][DM];
                #pragma unroll
                for(int j=0;j<6;j++){
                    const float* wp = Wl + (tid + 256*j)*DM;
                    #pragma unroll
                    for(int d=0;d<DM;d++) w[j][d]=wp[d];
                }
                for (int r=0;r<nr;r++){
                    float u[DM];
                    #pragma unroll
                    for(int d=0;d<DM;d++) u[d]=su[r*DM+d];
                    #pragma unroll
                    for(int j=0;j<6;j++){
                        float acc=0.f;
                        #pragma unroll
                        for(int d=0;d<DM;d++) acc += u[d]*w[j][d];
                        g_xz[(r0+r)*XZW + tid + 256*j] = acc;
                    }
                }
            }
        }
        gridbar();

        // ---- fused conv(3)+silu + silu(z) + x_proj (4 rows per warp-task) ----
        for (int task = bid*8 + warp; task < ROWS/4; task += NB*8){
            int rbase = task*4;
            int l0 = rbase % LP;
            const float* Wl = x_proj_w + layer*DBLW*ED;
            float part[4][DBLW];
            #pragma unroll
            for(int r=0;r<4;r++)
                #pragma unroll
                for(int t=0;t<DBLW;t++) part[r][t]=0.f;
            for (int k=0;k<ED/32;k++){
                int e = k*32 + lane;
                const float* wp = conv1d_w + (layer*ED + e)*3;
                float w0=wp[0], w1=wp[1], w2=wp[2];
                float bias = conv1d_b[layer*ED + e];
                float xv[6];
                xv[0] = (l0>=2) ? g_xz[(rbase-2)*XZW + e] : 0.f;
                xv[1] = (l0>=1) ? g_xz[(rbase-1)*XZW + e] : 0.f;
                #pragma unroll
                for(int r=0;r<4;r++) xv[2+r] = g_xz[(rbase+r)*XZW + e];
                float xc[4];
                #pragma unroll
                for(int r=0;r<4;r++){
                    float a = bias + w0*xv[r] + w1*xv[r+1] + w2*xv[r+2];
                    xc[r] = siluf_(a);
                    g_xc[(rbase+r)*ED + e] = xc[r];
                    float zv = g_xz[(rbase+r)*XZW + ED + e];
                    g_xz[(rbase+r)*XZW + ED + e] = siluf_(zv);
                }
                #pragma unroll
                for(int t=0;t<DBLW;t++){
                    float wv = __ldg(Wl + t*ED + e);
                    #pragma unroll
                    for(int r=0;r<4;r++) part[r][t] += xc[r]*wv;
                }
            }
            #pragma unroll
            for(int r=0;r<4;r++){
                #pragma unroll
                for(int t=0;t<DBLW;t++){
                    float v = part[r][t];
                    for(int off=16;off>0;off>>=1) v += __shfl_down_sync(0xffffffffu, v, off);
                    if (lane==0) g_dbl[(rbase+r)*DBLW + t] = v;
                }
            }
        }
        gridbar();

        // ---- fused scan + gate + out_proj ----
        {
            float* sdbl = sbuf;            // LP*DBLW
            float* sy   = sbuf + LP*DBLW;  // 48*192
            for (int task = bid; task < BSZ*4; task += NB){
                int b  = task >> 2;
                int ch = task & 3;
                bool act = (tid < 192);
                int e = ch*192 + (act ? tid : 191);
                int rowbase = b*LP;
                for (int t=tid; t<LP*DBLW; t+=256) sdbl[t] = g_dbl[rowbase*DBLW + t];

                float a2[NS];
                const float* ap = g_A2 + (layer*ED + e)*NS;
                #pragma unroll
                for(int n=0;n<NS;n++) a2[n]=ap[n];
                bool geo = true;
                #pragma unroll
                for(int n=1;n<NS;n++)
                    geo = geo && (fabsf(a2[n] - (float)(n+1)*a2[0]) <= 1e-4f*fabsf(a2[n]));
                float dw = dt_proj_w[layer*ED + e];
                float db = dt_proj_b[layer*ED + e];
                float Dv = Dp [layer*ED + e];
                // out_proj weight slice: cols ch*192 + lane + 32*j (all 8 warps identical)
                float wd[DM][6];
                #pragma unroll
                for(int d=0;d<DM;d++){
                    const float* wp = out_proj_w + (layer*DM + d)*ED + ch*192 + lane;
                    #pragma unroll
                    for(int j=0;j<6;j++) wd[d][j] = wp[32*j];
                }
                float st[NS];
                #pragma unroll
                for(int n=0;n<NS;n++) st[n]=0.f;
                __syncthreads();

                float xc_n = 0.f, sz_n = 0.f;
                if (act){
                    xc_n = g_xc[rowbase*ED + e];
                    sz_n = g_xz[rowbase*XZW + ED + e];
                }
                for (int ph=0; ph<2; ph++){
                    int lbeg = ph*48;
                    if (act){
                        for (int li=0; li<48; li++){
                            int l = lbeg + li;
                            float xc = xc_n, sz = sz_n;
                            int ln = (l<LP-1) ? l+1 : l;
                            xc_n = g_xc[(rowbase+ln)*ED + e];
                            sz_n = g_xz[(rowbase+ln)*XZW + ED + e];
                            const float* dl = sdbl + l*DBLW;
                            float delta = softplusf_(dl[0]*dw + db);
                            float dx = delta * xc;
                            float y  = Dv * xc;
                            float da[NS];
                            if (geo){
                                float p = ex2f_(delta * a2[0]);
                                da[0] = p;
                                #pragma unroll
                                for(int n=1;n<NS;n++) da[n] = da[n-1]*p;
                            } else {
                                #pragma unroll
                                for(int n=0;n<NS;n++) da[n] = ex2f_(delta * a2[n]);
                            }
                            #pragma unroll
                            for(int n=0;n<NS;n++){
                                st[n] = da[n]*st[n] + dx*dl[1+n];
                                y += st[n]*dl[9+n];
                            }
                            sy[li*192 + tid] = y * sz;
                        }
                    }
                    __syncthreads();
                    // out_proj partials: 8 warps x 6 = 48 rows
                    #pragma unroll
                    for (int kk=0; kk<6; kk++){
                        int li = kk*8 + warp;
                        float prt[DM];
                        #pragma unroll
                        for(int d=0;d<DM;d++) prt[d]=0.f;
                        #pragma unroll
                        for(int j=0;j<6;j++){
                            float yv = sy[li*192 + lane + 32*j];
                            #pragma unroll
                            for(int d=0;d<DM;d++) prt[d] += yv*wd[d][j];
                        }
                        #pragma unroll
                        for(int d=0;d<DM;d++){
                            float v = prt[d];
                            for(int off=16;off>0;off>>=1) v += __shfl_down_sync(0xffffffffu, v, off);
                            if (lane==0) atomicAdd(&g_h[(rowbase+lbeg+li)*DM + d], v);
                        }
                    }
                    __syncthreads();
                }
            }
        }
        gridbar();
    }

    // ===== final: mean over L + FC + ReLU =====
    {
        float* m = sbuf;
        for (int b = bid; b < BSZ; b += NB){
            if (tid < DM){
                float s=0.f;
                for(int l=0;l<LP;l++) s += g_h[(b*LP+l)*DM + tid];
                m[tid]=s*(1.0f/LP);
            }
            __syncthreads();
            float acc = fc_b[tid];
            #pragma unroll
            for(int d=0;d<DM;d++) acc += m[d]*fc_w[tid*DM+d];
            out[b*EMB+tid] = fmaxf(acc,0.0f);
            __syncthreads();
        }
    }
}

// ---------------- launch ----------------
extern "C" void kernel_launch(void* const* d_in, const int* in_sizes, int n_in,
                              void* d_out, int out_size){
    const float* x          = (const float*)d_in[0];
    const float* conv_re_w  = (const float*)d_in[1];
    const float* conv_re_b  = (const float*)d_in[2];
    const float* conv_im_w  = (const float*)d_in[3];
    const float* conv_im_b  = (const float*)d_in[4];
    const float* pos        = (const float*)d_in[5];
    const float* bn_gamma   = (const float*)d_in[6];
    const float* bn_beta    = (const float*)d_in[7];
    const float* rms_w      = (const float*)d_in[8];
    const float* in_proj_w  = (const float*)d_in[9];
    const float* conv1d_w   = (const float*)d_in[10];
    const float* conv1d_b   = (const float*)d_in[11];
    const float* x_proj_w   = (const float*)d_in[12];
    const float* dt_proj_w  = (const float*)d_in[13];
    const float* dt_proj_b  = (const float*)d_in[14];
    const float* A_log      = (const float*)d_in[15];
    const float* Dp         = (const float*)d_in[16];
    const float* out_proj_w = (const float*)d_in[17];
    const float* fc_w       = (const float*)d_in[18];
    const float* fc_b       = (const float*)d_in[19];
    float* out = (float*)d_out;

    int dev = 0; cudaGetDevice(&dev);
    int nsm = 148;
    cudaDeviceGetAttribute(&nsm, cudaDevAttrMultiProcessorCount, dev);
    if (nsm < 1) nsm = 1;
    if (nsm > 148) nsm = 148;

    k_mega<<<nsm, 256>>>(x, conv_re_w, conv_re_b, conv_im_w, conv_im_b, pos,
                         bn_gamma, bn_beta, rms_w, in_proj_w, conv1d_w, conv1d_b,
                         x_proj_w, dt_proj_w, dt_proj_b, A_log, Dp, out_proj_w,
                         fc_w, fc_b, out);
}

// round 7
// speedup vs baseline: 1.5602x; 1.2611x over previous
#include <cuda_runtime.h>

#define BSZ 32
#define LP 96
#define DM 12
#define ED 768
#define NS 8
#define NL 10
#define EMB 256
#define PP 50
#define ROWS (BSZ*LP)      // 3072
#define XZW (2*ED)         // 1536
#define DBLW 17            // DR + 2N
#define NTH 512

// ---------------- scratch ----------------
__device__ float g_h[ROWS*DM];
__device__ float g_xz[ROWS*XZW];
__device__ float g_xc[ROWS*ED];
__device__ float g_dbl[ROWS*DBLW];
__device__ float g_A2[NL*ED*NS];
__device__ float g_bns[2*DM];
__device__ volatile unsigned g_bar_gen;
__device__ unsigned g_bar_cnt;

// ---------------- fast math ----------------
__device__ __forceinline__ float ex2f_(float x){ float y; asm("ex2.approx.f32 %0, %1;":"=f"(y):"f"(x)); return y; }
__device__ __forceinline__ float lg2f_(float x){ float y; asm("lg2.approx.f32 %0, %1;":"=f"(y):"f"(x)); return y; }
__device__ __forceinline__ float rcpf_(float x){ float y; asm("rcp.approx.f32 %0, %1;":"=f"(y):"f"(x)); return y; }
#define L2E 1.4426950408889634f
#define LN2 0.6931471805599453f
__device__ __forceinline__ float sigmoidf_(float x){ return rcpf_(1.0f + ex2f_(-x*L2E)); }
__device__ __forceinline__ float siluf_(float x){ return x * sigmoidf_(x); }
__device__ __forceinline__ float softplusf_(float x){
    return (x > 20.0f) ? x : LN2*lg2f_(1.0f + ex2f_(x*L2E));
}

// ---------------- grid barrier (grid == #SMs, 1 block/SM guaranteed) ----------------
__device__ __forceinline__ void gridbar(){
    __syncthreads();
    if (threadIdx.x == 0){
        __threadfence();
        unsigned gen = g_bar_gen;
        unsigned old = atomicAdd(&g_bar_cnt, 1u);
        if (old == gridDim.x - 1u){
            g_bar_cnt = 0u;
            __threadfence();
            g_bar_gen = gen + 1u;
        } else {
            while (g_bar_gen == gen) __nanosleep(20);
        }
        __threadfence();
    }
    __syncthreads();
}

// ---------------- the megakernel ----------------
__global__ void __launch_bounds__(NTH) k_mega(
    const float* __restrict__ x,
    const float* __restrict__ conv_re_w, const float* __restrict__ conv_re_b,
    const float* __restrict__ conv_im_w, const float* __restrict__ conv_im_b,
    const float* __restrict__ pos,
    const float* __restrict__ bn_gamma, const float* __restrict__ bn_beta,
    const float* __restrict__ rms_w,
    const float* __restrict__ in_proj_w,
    const float* __restrict__ conv1d_w, const float* __restrict__ conv1d_b,
    const float* __restrict__ x_proj_w,
    const float* __restrict__ dt_proj_w, const float* __restrict__ dt_proj_b,
    const float* __restrict__ A_log,  const float* __restrict__ Dp,
    const float* __restrict__ out_proj_w,
    const float* __restrict__ fc_w, const float* __restrict__ fc_b,
    float* __restrict__ out)
{
    __shared__ float sbuf[LP*DBLW + 48*192];   // 43392 B, reused per phase
    const int NB  = gridDim.x;
    const int bid = blockIdx.x;
    const int tid = threadIdx.x;
    const int gsz = NB*NTH;
    const int gtid = bid*NTH + tid;
    const int warp = tid >> 5, lane = tid & 31;

    // ===== phase 0: A2 prep + front-end + zero BN accumulators =====
    for (int i = gtid; i < NL*ED*NS; i += gsz) g_A2[i] = -expf(A_log[i]) * L2E;
    if (gtid < 2*DM) g_bns[gtid] = 0.f;
    for (int idx = gtid; idx < ROWS*DM; idx += gsz){
        int row = idx / DM, o = idx % DM;
        int b = row / LP, l = row % LP;
        const float* xr = x + b*(2*LP*PP) + l*PP;
        const float* xi = xr + LP*PP;
        float acc;
        if (o < 6){
            acc = conv_re_b[o] - conv_im_b[o];
            const float* w1 = conv_re_w + o*PP; const float* w2 = conv_im_w + o*PP;
            #pragma unroll 10
            for (int k=0;k<PP;k++) acc += xr[k]*w1[k] - xi[k]*w2[k];
        } else {
            int o6 = o-6;
            acc = conv_re_b[o6] + conv_im_b[o6];
            const float* w1 = conv_re_w + o6*PP; const float* w2 = conv_im_w + o6*PP;
            #pragma unroll 10
            for (int k=0;k<PP;k++) acc += xi[k]*w1[k] + xr[k]*w2[k];
        }
        g_h[idx] = acc + pos[l*DM + o];
    }
    gridbar();

    // ===== BN: global sums =====
    {
        float ls[DM], lq[DM];
        #pragma unroll
        for(int c=0;c<DM;c++){ ls[c]=0.f; lq[c]=0.f; }
        for (int j = gtid; j < ROWS; j += gsz){
            #pragma unroll
            for(int c=0;c<DM;c++){ float v=g_h[j*DM+c]; ls[c]+=v; lq[c]+=v*v; }
        }
        #pragma unroll
        for(int c=0;c<DM;c++){
            float a=ls[c], q=lq[c];
            for(int off=16;off>0;off>>=1){
                a+=__shfl_down_sync(0xffffffffu,a,off);
                q+=__shfl_down_sync(0xffffffffu,q,off);
            }
            if (lane==0 && (a!=0.f || q!=0.f)){
                atomicAdd(&g_bns[c], a);
                atomicAdd(&g_bns[DM+c], q);
            }
        }
    }
    gridbar();

    // ===== BN: apply + silu =====
    {
        if (tid < DM){
            float mu  = g_bns[tid]*(1.0f/ROWS);
            float var = g_bns[DM+tid]*(1.0f/ROWS) - mu*mu;
            float sc  = rsqrtf(var+1e-6f)*bn_gamma[tid];
            sbuf[tid]     = sc;
            sbuf[DM+tid]  = bn_beta[tid] - mu*sc;
        }
        __syncthreads();
        for (int idx = gtid; idx < ROWS*DM; idx += gsz){
            int c = idx % DM;
            float v = g_h[idx]*sbuf[c] + sbuf[DM+c];
            g_h[idx] = siluf_(v);
        }
    }
    gridbar();

    // ===== layers =====
    for (int layer = 0; layer < NL; layer++){
        // ---- rmsnorm + in_proj: 3 cols/thread ----
        {
            float* su   = sbuf;            // up to 24 rows * DM
            float* srms = sbuf + 24*DM;
            int rb = (ROWS + NB - 1)/NB;   // 21 for NB=148
            int r0 = bid*rb;
            int nr = ROWS - r0; if (nr > rb) nr = rb;
            if (nr > 0){
                const float* Wl  = in_proj_w + layer*XZW*DM;
                const float* rwl = rms_w + layer*DM;
                for (int t=tid; t<nr*DM; t+=NTH) su[t] = g_h[r0*DM + t];
                __syncthreads();
                if (tid < nr){
                    float s=0.f;
                    #pragma unroll
                    for(int d=0;d<DM;d++){ float v=su[tid*DM+d]; s+=v*v; }
                    srms[tid] = rsqrtf(s*(1.0f/DM)+1e-5f);
                }
                __syncthreads();
                for (int t=tid; t<nr*DM; t+=NTH) su[t] = su[t]*srms[t/DM]*rwl[t%DM];
                __syncthreads();
                float w[3][DM];
                #pragma unroll
                for(int j=0;j<3;j++){
                    const float* wp = Wl + (tid + NTH*j)*DM;
                    #pragma unroll
                    for(int d=0;d<DM;d++) w[j][d]=wp[d];
                }
                for (int r=0;r<nr;r++){
                    float u[DM];
                    #pragma unroll
                    for(int d=0;d<DM;d++) u[d]=su[r*DM+d];
                    #pragma unroll
                    for(int j=0;j<3;j++){
                        float acc=0.f;
                        #pragma unroll
                        for(int d=0;d<DM;d++) acc += u[d]*w[j][d];
                        g_xz[(r0+r)*XZW + tid + NTH*j] = acc;
                    }
                }
            }
        }
        gridbar();

        // ---- fused conv(3)+silu + silu(z) + x_proj: 2 rows per warp-task ----
        for (int task = bid*16 + warp; task < ROWS/2; task += NB*16){
            int rbase = task*2;
            int l0 = rbase % LP;
            const float* Wl = x_proj_w + layer*DBLW*ED;
            float part[2][DBLW];
            #pragma unroll
            for(int r=0;r<2;r++)
                #pragma unroll
                for(int t=0;t<DBLW;t++) part[r][t]=0.f;
            for (int k=0;k<ED/32;k++){
                int e = k*32 + lane;
                const float* wp = conv1d_w + (layer*ED + e)*3;
                float w0=wp[0], w1=wp[1], w2=wp[2];
                float bias = conv1d_b[layer*ED + e];
                float xv[4];
                xv[0] = (l0>=2) ? g_xz[(rbase-2)*XZW + e] : 0.f;
                xv[1] = (l0>=1) ? g_xz[(rbase-1)*XZW + e] : 0.f;
                xv[2] = g_xz[(rbase  )*XZW + e];
                xv[3] = g_xz[(rbase+1)*XZW + e];
                float xc[2];
                #pragma unroll
                for(int r=0;r<2;r++){
                    float a = bias + w0*xv[r] + w1*xv[r+1] + w2*xv[r+2];
                    xc[r] = siluf_(a);
                    g_xc[(rbase+r)*ED + e] = xc[r];
                    float zv = g_xz[(rbase+r)*XZW + ED + e];
                    g_xz[(rbase+r)*XZW + ED + e] = siluf_(zv);
                }
                #pragma unroll
                for(int t=0;t<DBLW;t++){
                    float wv = __ldg(Wl + t*ED + e);
                    #pragma unroll
                    for(int r=0;r<2;r++) part[r][t] += xc[r]*wv;
                }
            }
            #pragma unroll
            for(int r=0;r<2;r++){
                #pragma unroll
                for(int t=0;t<DBLW;t++){
                    float v = part[r][t];
                    for(int off=16;off>0;off>>=1) v += __shfl_down_sync(0xffffffffu, v, off);
                    if (lane==0) g_dbl[(rbase+r)*DBLW + t] = v;
                }
            }
        }
        gridbar();

        // ---- fused scan + gate + out_proj (128 tasks; block = one task) ----
        if (bid < BSZ*4){
            float* sdbl = sbuf;            // LP*DBLW
            float* sy   = sbuf + LP*DBLW;  // 48*192
            int b  = bid >> 2;
            int ch = bid & 3;
            bool act = (tid < 192);
            int e = ch*192 + (act ? tid : 191);
            int rowbase = b*LP;
            for (int t=tid; t<LP*DBLW; t+=NTH) sdbl[t] = g_dbl[rowbase*DBLW + t];

            float a2[NS];
            const float* ap = g_A2 + (layer*ED + e)*NS;
            #pragma unroll
            for(int n=0;n<NS;n++) a2[n]=ap[n];
            bool geo = true;
            #pragma unroll
            for(int n=1;n<NS;n++)
                geo = geo && (fabsf(a2[n] - (float)(n+1)*a2[0]) <= 1e-4f*fabsf(a2[n]));
            float dw = dt_proj_w[layer*ED + e];
            float db = dt_proj_b[layer*ED + e];
            float Dv = Dp [layer*ED + e];
            // out_proj weight slice: cols ch*192 + lane + 32*j (all warps identical)
            float wd[DM][6];
            #pragma unroll
            for(int d=0;d<DM;d++){
                const float* wp = out_proj_w + (layer*DM + d)*ED + ch*192 + lane;
                #pragma unroll
                for(int j=0;j<6;j++) wd[d][j] = wp[32*j];
            }
            float st[NS];
            #pragma unroll
            for(int n=0;n<NS;n++) st[n]=0.f;
            __syncthreads();

            float xc_n = 0.f, sz_n = 0.f;
            if (act){
                xc_n = g_xc[rowbase*ED + e];
                sz_n = g_xz[rowbase*XZW + ED + e];
            }
            for (int ph=0; ph<2; ph++){
                int lbeg = ph*48;
                if (act){
                    for (int li=0; li<48; li++){
                        int l = lbeg + li;
                        float xc = xc_n, sz = sz_n;
                        int ln = (l<LP-1) ? l+1 : l;
                        xc_n = g_xc[(rowbase+ln)*ED + e];
                        sz_n = g_xz[(rowbase+ln)*XZW + ED + e];
                        const float* dl = sdbl + l*DBLW;
                        float delta = softplusf_(dl[0]*dw + db);
                        float dx = delta * xc;
                        float y  = Dv * xc;
                        float da[NS];
                        if (geo){
                            float p = ex2f_(delta * a2[0]);
                            da[0] = p;
                            #pragma unroll
                            for(int n=1;n<NS;n++) da[n] = da[n-1]*p;
                        } else {
                            #pragma unroll
                            for(int n=0;n<NS;n++) da[n] = ex2f_(delta * a2[n]);
                        }
                        #pragma unroll
                        for(int n=0;n<NS;n++){
                            st[n] = da[n]*st[n] + dx*dl[1+n];
                            y += st[n]*dl[9+n];
                        }
                        sy[li*192 + tid] = y * sz;
                    }
                }
                __syncthreads();
                // out_proj partials: 16 warps x 3 = 48 rows
                #pragma unroll
                for (int kk=0; kk<3; kk++){
                    int li = kk*16 + warp;
                    float prt[DM];
                    #pragma unroll
                    for(int d=0;d<DM;d++) prt[d]=0.f;
                    #pragma unroll
                    for(int j=0;j<6;j++){
                        float yv = sy[li*192 + lane + 32*j];
                        #pragma unroll
                        for(int d=0;d<DM;d++) prt[d] += yv*wd[d][j];
                    }
                    #pragma unroll
                    for(int d=0;d<DM;d++){
                        float v = prt[d];
                        for(int off=16;off>0;off>>=1) v += __shfl_down_sync(0xffffffffu, v, off);
                        if (lane==0) atomicAdd(&g_h[(rowbase+lbeg+li)*DM + d], v);
                    }
                }
                __syncthreads();
            }
        }
        gridbar();
    }

    // ===== final: mean over L + FC + ReLU =====
    {
        float* m = sbuf;
        for (int b = bid; b < BSZ; b += NB){
            if (tid < DM){
                float s=0.f;
                for(int l=0;l<LP;l++) s += g_h[(b*LP+l)*DM + tid];
                m[tid]=s*(1.0f/LP);
            }
            __syncthreads();
            if (tid < EMB){
                float acc = fc_b[tid];
                #pragma unroll
                for(int d=0;d<DM;d++) acc += m[d]*fc_w[tid*DM+d];
                out[b*EMB+tid] = fmaxf(acc,0.0f);
            }
            __syncthreads();
        }
    }
}

// ---------------- launch ----------------
extern "C" void kernel_launch(void* const* d_in, const int* in_sizes, int n_in,
                              void* d_out, int out_size){
    const float* x          = (const float*)d_in[0];
    const float* conv_re_w  = (const float*)d_in[1];
    const float* conv_re_b  = (const float*)d_in[2];
    const float* conv_im_w  = (const float*)d_in[3];
    const float* conv_im_b  = (const float*)d_in[4];
    const float* pos        = (const float*)d_in[5];
    const float* bn_gamma   = (const float*)d_in[6];
    const float* bn_beta    = (const float*)d_in[7];
    const float* rms_w      = (const float*)d_in[8];
    const float* in_proj_w  = (const float*)d_in[9];
    const float* conv1d_w   = (const float*)d_in[10];
    const float* conv1d_b   = (const float*)d_in[11];
    const float* x_proj_w   = (const float*)d_in[12];
    const float* dt_proj_w  = (const float*)d_in[13];
    const float* dt_proj_b  = (const float*)d_in[14];
    const float* A_log      = (const float*)d_in[15];
    const float* Dp         = (const float*)d_in[16];
    const float* out_proj_w = (const float*)d_in[17];
    const float* fc_w       = (const float*)d_in[18];
    const float* fc_b       = (const float*)d_in[19];
    float* out = (float*)d_out;

    int dev = 0; cudaGetDevice(&dev);
    int nsm = 148;
    cudaDeviceGetAttribute(&nsm, cudaDevAttrMultiProcessorCount, dev);
    if (nsm < 1) nsm = 1;
    if (nsm > 148) nsm = 148;

    k_mega<<<nsm, NTH>>>(x, conv_re_w, conv_re_b, conv_im_w, conv_im_b, pos,
                         bn_gamma, bn_beta, rms_w, in_proj_w, conv1d_w, conv1d_b,
                         x_proj_w, dt_proj_w, dt_proj_b, A_log, Dp, out_proj_w,
                         fc_w, fc_b, out);
}

// round 8
// speedup vs baseline: 1.5898x; 1.0189x over previous
#include <cuda_runtime.h>

#define BSZ 32
#define LP 96
#define DM 12
#define ED 768
#define NS 8
#define NL 10
#define EMB 256
#define PP 50
#define ROWS (BSZ*LP)      // 3072
#define XZW (2*ED)         // 1536
#define DBLW 17            // DR + 2N
#define NTH 768
#define NSEG 4
#define SEGL 24
#define DYNF (2*SEGL*ED + SEGL*DBLW + 64)   // floats of dynamic smem

// ---------------- scratch ----------------
__device__ float g_h[ROWS*DM];
__device__ float g_xz[ROWS*XZW];
__device__ float g_xc[ROWS*ED];
__device__ float g_dbl[ROWS*DBLW];
__device__ float g_y[ROWS*ED];
__device__ float g_P[3*BSZ*NS*ED];    // segment transfer products (segs 0..2)
__device__ float g_q[3*BSZ*NS*ED];    // segment end states (zero-init)
__device__ float g_A2[NL*ED*NS];
__device__ float g_bns[2*DM];
__device__ volatile unsigned g_bar_gen;
__device__ unsigned g_bar_cnt;

// ---------------- fast math ----------------
__device__ __forceinline__ float ex2f_(float x){ float y; asm("ex2.approx.f32 %0, %1;":"=f"(y):"f"(x)); return y; }
__device__ __forceinline__ float lg2f_(float x){ float y; asm("lg2.approx.f32 %0, %1;":"=f"(y):"f"(x)); return y; }
__device__ __forceinline__ float rcpf_(float x){ float y; asm("rcp.approx.f32 %0, %1;":"=f"(y):"f"(x)); return y; }
#define L2E 1.4426950408889634f
#define LN2 0.6931471805599453f
__device__ __forceinline__ float sigmoidf_(float x){ return rcpf_(1.0f + ex2f_(-x*L2E)); }
__device__ __forceinline__ float siluf_(float x){ return x * sigmoidf_(x); }
__device__ __forceinline__ float softplusf_(float x){
    return (x > 20.0f) ? x : LN2*lg2f_(1.0f + ex2f_(x*L2E));
}

// ---------------- grid barrier (grid == #SMs, 1 block/SM guaranteed) ----------------
__device__ __forceinline__ void gridbar(){
    __syncthreads();
    if (threadIdx.x == 0){
        __threadfence();
        unsigned gen = g_bar_gen;
        unsigned old = atomicAdd(&g_bar_cnt, 1u);
        if (old == gridDim.x - 1u){
            g_bar_cnt = 0u;
            __threadfence();
            g_bar_gen = gen + 1u;
        } else {
            while (g_bar_gen == gen) __nanosleep(20);
        }
        __threadfence();
    }
    __syncthreads();
}

// ---------------- megakernel ----------------
__global__ void __launch_bounds__(NTH,1) k_mega(
    const float* __restrict__ x,
    const float* __restrict__ conv_re_w, const float* __restrict__ conv_re_b,
    const float* __restrict__ conv_im_w, const float* __restrict__ conv_im_b,
    const float* __restrict__ pos,
    const float* __restrict__ bn_gamma, const float* __restrict__ bn_beta,
    const float* __restrict__ rms_w,
    const float* __restrict__ in_proj_w,
    const float* __restrict__ conv1d_w, const float* __restrict__ conv1d_b,
    const float* __restrict__ x_proj_w,
    const float* __restrict__ dt_proj_w, const float* __restrict__ dt_proj_b,
    const float* __restrict__ A_log,  const float* __restrict__ Dp,
    const float* __restrict__ out_proj_w,
    const float* __restrict__ fc_w, const float* __restrict__ fc_b,
    float* __restrict__ out)
{
    extern __shared__ float sdyn[];
    const int NB  = gridDim.x;
    const int bid = blockIdx.x;
    const int tid = threadIdx.x;
    const int gsz = NB*NTH;
    const int gtid = bid*NTH + tid;
    const int warp = tid >> 5, lane = tid & 31;

    // block-aligned row range (shared by inproj and outproj so they need no grid bar)
    const int rb = (ROWS + NB - 1)/NB;          // 21 for NB=148
    const int r0 = bid*rb;
    int nr = ROWS - r0; if (nr > rb) nr = rb; if (nr < 0) nr = 0;

    // ===== phase 0: A2 prep + front-end + zero BN accumulators =====
    for (int i = gtid; i < NL*ED*NS; i += gsz) g_A2[i] = -expf(A_log[i]) * L2E;
    if (gtid < 2*DM) g_bns[gtid] = 0.f;
    for (int idx = gtid; idx < ROWS*DM; idx += gsz){
        int row = idx / DM, o = idx % DM;
        int b = row / LP, l = row % LP;
        const float* xr = x + b*(2*LP*PP) + l*PP;
        const float* xi = xr + LP*PP;
        float acc;
        if (o < 6){
            acc = conv_re_b[o] - conv_im_b[o];
            const float* w1 = conv_re_w + o*PP; const float* w2 = conv_im_w + o*PP;
            #pragma unroll 10
            for (int k=0;k<PP;k++) acc += xr[k]*w1[k] - xi[k]*w2[k];
        } else {
            int o6 = o-6;
            acc = conv_re_b[o6] + conv_im_b[o6];
            const float* w1 = conv_re_w + o6*PP; const float* w2 = conv_im_w + o6*PP;
            #pragma unroll 10
            for (int k=0;k<PP;k++) acc += xi[k]*w1[k] + xr[k]*w2[k];
        }
        g_h[idx] = acc + pos[l*DM + o];
    }
    gridbar();

    // ===== BN: global sums =====
    {
        float ls[DM], lq[DM];
        #pragma unroll
        for(int c=0;c<DM;c++){ ls[c]=0.f; lq[c]=0.f; }
        for (int j = gtid; j < ROWS; j += gsz){
            #pragma unroll
            for(int c=0;c<DM;c++){ float v=g_h[j*DM+c]; ls[c]+=v; lq[c]+=v*v; }
        }
        #pragma unroll
        for(int c=0;c<DM;c++){
            float a=ls[c], q=lq[c];
            for(int off=16;off>0;off>>=1){
                a+=__shfl_down_sync(0xffffffffu,a,off);
                q+=__shfl_down_sync(0xffffffffu,q,off);
            }
            if (lane==0 && (a!=0.f || q!=0.f)){
                atomicAdd(&g_bns[c], a);
                atomicAdd(&g_bns[DM+c], q);
            }
        }
    }
    gridbar();

    // ===== BN: apply + silu =====
    {
        if (tid < DM){
            float mu  = g_bns[tid]*(1.0f/ROWS);
            float var = g_bns[DM+tid]*(1.0f/ROWS) - mu*mu;
            float sc  = rsqrtf(var+1e-6f)*bn_gamma[tid];
            sdyn[tid]    = sc;
            sdyn[DM+tid] = bn_beta[tid] - mu*sc;
        }
        __syncthreads();
        for (int idx = gtid; idx < ROWS*DM; idx += gsz){
            int c = idx % DM;
            float v = g_h[idx]*sdyn[c] + sdyn[DM+c];
            g_h[idx] = siluf_(v);
        }
        __syncthreads();
    }
    gridbar();

    // ===== layers =====
    for (int layer = 0; layer < NL; layer++){
        // ---- rmsnorm + in_proj (rows r0..r0+nr-1, 2 cols/thread) ----
        {
            float* su   = sdyn;            // nr*DM
            float* srms = sdyn + 24*DM;
            if (nr > 0){
                const float* Wl  = in_proj_w + layer*XZW*DM;
                const float* rwl = rms_w + layer*DM;
                for (int t=tid; t<nr*DM; t+=NTH) su[t] = g_h[r0*DM + t];
                __syncthreads();
                if (tid < nr){
                    float s=0.f;
                    #pragma unroll
                    for(int d=0;d<DM;d++){ float v=su[tid*DM+d]; s+=v*v; }
                    srms[tid] = rsqrtf(s*(1.0f/DM)+1e-5f);
                }
                __syncthreads();
                for (int t=tid; t<nr*DM; t+=NTH) su[t] = su[t]*srms[t/DM]*rwl[t%DM];
                __syncthreads();
                float w[2][DM];
                #pragma unroll
                for(int j=0;j<2;j++){
                    const float* wp = Wl + (tid + NTH*j)*DM;
                    #pragma unroll
                    for(int d=0;d<DM;d++) w[j][d]=wp[d];
                }
                for (int r=0;r<nr;r++){
                    float u[DM];
                    #pragma unroll
                    for(int d=0;d<DM;d++) u[d]=su[r*DM+d];
                    #pragma unroll
                    for(int j=0;j<2;j++){
                        float acc=0.f;
                        #pragma unroll
                        for(int d=0;d<DM;d++) acc += u[d]*w[j][d];
                        g_xz[(r0+r)*XZW + tid + NTH*j] = acc;
                    }
                }
            }
        }
        gridbar();

        // ---- fused conv(3)+silu + silu(z) + x_proj: 1 row per warp ----
        for (int row = bid*24 + warp; row < ROWS; row += NB*24){
            int l0 = row % LP;
            const float* Wl = x_proj_w + layer*DBLW*ED;
            float part[DBLW];
            #pragma unroll
            for(int t=0;t<DBLW;t++) part[t]=0.f;
            for (int k=0;k<ED/32;k++){
                int e = k*32 + lane;
                const float* wp = conv1d_w + (layer*ED + e)*3;
                float w0=wp[0], w1=wp[1], w2=wp[2];
                float bias = conv1d_b[layer*ED + e];
                float xm2 = (l0>=2) ? g_xz[(row-2)*XZW + e] : 0.f;
                float xm1 = (l0>=1) ? g_xz[(row-1)*XZW + e] : 0.f;
                float x0  = g_xz[row*XZW + e];
                float a = bias + w0*xm2 + w1*xm1 + w2*x0;
                float xc = siluf_(a);
                g_xc[row*ED + e] = xc;
                float zv = g_xz[row*XZW + ED + e];
                g_xz[row*XZW + ED + e] = siluf_(zv);
                #pragma unroll
                for(int t=0;t<DBLW;t++) part[t] += xc*__ldg(Wl + t*ED + e);
            }
            #pragma unroll
            for(int t=0;t<DBLW;t++){
                float v = part[t];
                for(int off=16;off>0;off>>=1) v += __shfl_down_sync(0xffffffffu, v, off);
                if (lane==0) g_dbl[row*DBLW + t] = v;
            }
        }
        gridbar();

        // ---- scan stage A: per (b,e,seg<3) compute (P, q) ----
        for (int idx = gtid; idx < 3*BSZ*ED; idx += gsz){
            int e = idx % ED; int t2 = idx / ED;
            int b = t2 % BSZ; int s = t2 / BSZ;      // s in 0..2
            float a2[NS];
            const float* ap = g_A2 + (layer*ED + e)*NS;
            #pragma unroll
            for(int n=0;n<NS;n++) a2[n]=ap[n];
            bool geo = true;
            #pragma unroll
            for(int n=1;n<NS;n++)
                geo = geo && (fabsf(a2[n] - (float)(n+1)*a2[0]) <= 1e-4f*fabsf(a2[n]));
            float dw = dt_proj_w[layer*ED + e];
            float db = dt_proj_b[layer*ED + e];
            float st[NS], Pr[NS];
            #pragma unroll
            for(int n=0;n<NS;n++){ st[n]=0.f; Pr[n]=1.f; }
            int rowbase = b*LP + s*SEGL;
            for (int li=0; li<SEGL; li++){
                int row = rowbase + li;
                float xc = g_xc[row*ED + e];
                const float* dl = g_dbl + row*DBLW;
                float delta = softplusf_(dl[0]*dw + db);
                float dx = delta * xc;
                float p = ex2f_(delta * a2[0]);
                float dan = 1.f;
                #pragma unroll
                for(int n=0;n<NS;n++){
                    if (geo) dan *= p;
                    else     dan = ex2f_(delta * a2[n]);
                    st[n] = dan*st[n] + dx*dl[1+n];
                    Pr[n] *= dan;
                }
            }
            int base = ((s*BSZ + b)*NS)*ED + e;
            #pragma unroll
            for(int n=0;n<NS;n++){
                g_P[base + n*ED] = Pr[n];
                g_q[base + n*ED] = st[n];
            }
        }
        gridbar();

        // ---- scan stage C: block = (b,seg), 768 e's, smem-staged inputs ----
        for (int task = bid; task < BSZ*NSEG; task += NB){
            int b = task >> 2;
            int s = task & 3;
            int rowbase = b*LP + s*SEGL;
            float* sxc  = sdyn;                  // SEGL*ED
            float* szv  = sdyn + SEGL*ED;        // SEGL*ED
            float* sdbl = sdyn + 2*SEGL*ED;      // SEGL*DBLW
            for (int r=0; r<SEGL; r++){
                sxc[r*ED + tid] = g_xc[(rowbase+r)*ED + tid];
                szv[r*ED + tid] = g_xz[(rowbase+r)*XZW + ED + tid];
            }
            for (int t=tid; t<SEGL*DBLW; t+=NTH) sdbl[t] = g_dbl[rowbase*DBLW + t];
            int e = tid;
            float a2[NS];
            const float* ap = g_A2 + (layer*ED + e)*NS;
            #pragma unroll
            for(int n=0;n<NS;n++) a2[n]=ap[n];
            bool geo = true;
            #pragma unroll
            for(int n=1;n<NS;n++)
                geo = geo && (fabsf(a2[n] - (float)(n+1)*a2[0]) <= 1e-4f*fabsf(a2[n]));
            float dw = dt_proj_w[layer*ED + e];
            float db = dt_proj_b[layer*ED + e];
            float Dv = Dp [layer*ED + e];
            // compose initial state from previous segments (exact transfer pairs)
            float hn[NS];
            #pragma unroll
            for(int n=0;n<NS;n++) hn[n]=0.f;
            for (int sp=0; sp<s; sp++){
                int base = ((sp*BSZ + b)*NS)*ED + e;
                #pragma unroll
                for(int n=0;n<NS;n++)
                    hn[n] = g_P[base + n*ED]*hn[n] + g_q[base + n*ED];
            }
            __syncthreads();
            for (int li=0; li<SEGL; li++){
                const float* dl = sdbl + li*DBLW;
                float xc = sxc[li*ED + tid];
                float sz = szv[li*ED + tid];
                float delta = softplusf_(dl[0]*dw + db);
                float dx = delta * xc;
                float y  = Dv * xc;
                float p = ex2f_(delta * a2[0]);
                float dan = 1.f;
                #pragma unroll
                for(int n=0;n<NS;n++){
                    if (geo) dan *= p;
                    else     dan = ex2f_(delta * a2[n]);
                    hn[n] = dan*hn[n] + dx*dl[1+n];
                    y += hn[n]*dl[9+n];
                }
                g_y[(rowbase+li)*ED + tid] = y * sz;
            }
            __syncthreads();
        }
        gridbar();

        // ---- out_proj: warp per owned row (block-aligned with inproj) ----
        for (int w = warp; w < nr; w += 24){
            int row = r0 + w;
            const float* Wl = out_proj_w + layer*DM*ED;
            float prt[DM];
            #pragma unroll
            for(int d=0;d<DM;d++) prt[d]=0.f;
            for (int k=lane; k<ED; k+=32){
                float yv = g_y[row*ED + k];
                #pragma unroll
                for(int d=0;d<DM;d++) prt[d] += yv*__ldg(Wl + d*ED + k);
            }
            #pragma unroll
            for(int d=0;d<DM;d++){
                float v = prt[d];
                for(int off=16;off>0;off>>=1) v += __shfl_down_sync(0xffffffffu, v, off);
                if (lane==0) g_h[row*DM + d] += v;
            }
        }
        __syncthreads();   // outproj -> next inproj touches only this block's rows
    }
    gridbar();

    // ===== final: mean over L + FC + ReLU =====
    {
        float* m = sdyn;
        for (int b = bid; b < BSZ; b += NB){
            if (tid < DM){
                float s=0.f;
                for(int l=0;l<LP;l++) s += g_h[(b*LP+l)*DM + tid];
                m[tid]=s*(1.0f/LP);
            }
            __syncthreads();
            if (tid < EMB){
                float acc = fc_b[tid];
                #pragma unroll
                for(int d=0;d<DM;d++) acc += m[d]*fc_w[tid*DM+d];
                out[b*EMB+tid] = fmaxf(acc,0.0f);
            }
            __syncthreads();
        }
    }
}

// ---------------- launch ----------------
extern "C" void kernel_launch(void* const* d_in, const int* in_sizes, int n_in,
                              void* d_out, int out_size){
    const float* x          = (const float*)d_in[0];
    const float* conv_re_w  = (const float*)d_in[1];
    const float* conv_re_b  = (const float*)d_in[2];
    const float* conv_im_w  = (const float*)d_in[3];
    const float* conv_im_b  = (const float*)d_in[4];
    const float* pos        = (const float*)d_in[5];
    const float* bn_gamma   = (const float*)d_in[6];
    const float* bn_beta    = (const float*)d_in[7];
    const float* rms_w      = (const float*)d_in[8];
    const float* in_proj_w  = (const float*)d_in[9];
    const float* conv1d_w   = (const float*)d_in[10];
    const float* conv1d_b   = (const float*)d_in[11];
    const float* x_proj_w   = (const float*)d_in[12];
    const float* dt_proj_w  = (const float*)d_in[13];
    const float* dt_proj_b  = (const float*)d_in[14];
    const float* A_log      = (const float*)d_in[15];
    const float* Dp         = (const float*)d_in[16];
    const float* out_proj_w = (const float*)d_in[17];
    const float* fc_w       = (const float*)d_in[18];
    const float* fc_b       = (const float*)d_in[19];
    float* out = (float*)d_out;

    int dev = 0; cudaGetDevice(&dev);
    int nsm = 148;
    cudaDeviceGetAttribute(&nsm, cudaDevAttrMultiProcessorCount, dev);
    if (nsm < 1) nsm = 1;
    if (nsm > 148) nsm = 148;

    size_t dynbytes = (size_t)DYNF * sizeof(float);
    cudaFuncSetAttribute(k_mega, cudaFuncAttributeMaxDynamicSharedMemorySize, (int)dynbytes);

    k_mega<<<nsm, NTH, dynbytes>>>(x, conv_re_w, conv_re_b, conv_im_w, conv_im_b, pos,
                         bn_gamma, bn_beta, rms_w, in_proj_w, conv1d_w, conv1d_b,
                         x_proj_w, dt_proj_w, dt_proj_b, A_log, Dp, out_proj_w,
                         fc_w, fc_b, out);
}

// round 9
// speedup vs baseline: 2.6954x; 1.6955x over previous
#include <cuda_runtime.h>

#define BSZ 32
#define LP 96
#define DM 12
#define ED 768
#define NS 8
#define NL 10
#define EMB 256
#define PP 50
#define ROWS (BSZ*LP)      // 3072
#define XZW (2*ED)         // 1536
#define DBLW 17
#define NTH 768
#define NBLK 128
#define SEGL 24
// dynamic smem: sxc[24*768] | ssz[24*768] | sdbl[24*17] | spare
#define DYNF (SEGL*ED*2 + SEGL*DBLW + 64)

// ---------------- scratch ----------------
__device__ __align__(16) float g_h[ROWS*DM];
__device__ __align__(16) float g_xz[ROWS*XZW];
__device__ __align__(16) float g_P[3*BSZ*NS*ED];
__device__ __align__(16) float g_q[3*BSZ*NS*ED];
__device__ __align__(16) float g_A2[NL*ED*NS];
__device__ __align__(16) float g_cwT[NL*4*ED];   // [layer][{w0,w1,w2,bias}][e]
__device__ float g_bns[2*DM];
__device__ volatile unsigned g_bar_gen;
__device__ unsigned g_bar_cnt;

// ---------------- fast math ----------------
__device__ __forceinline__ float ex2f_(float x){ float y; asm("ex2.approx.f32 %0, %1;":"=f"(y):"f"(x)); return y; }
__device__ __forceinline__ float lg2f_(float x){ float y; asm("lg2.approx.f32 %0, %1;":"=f"(y):"f"(x)); return y; }
__device__ __forceinline__ float rcpf_(float x){ float y; asm("rcp.approx.f32 %0, %1;":"=f"(y):"f"(x)); return y; }
#define L2E 1.4426950408889634f
#define LN2 0.6931471805599453f
__device__ __forceinline__ float sigmoidf_(float x){ return rcpf_(1.0f + ex2f_(-x*L2E)); }
__device__ __forceinline__ float siluf_(float x){ return x * sigmoidf_(x); }
__device__ __forceinline__ float softplusf_(float x){
    return (x > 20.0f) ? x : LN2*lg2f_(1.0f + ex2f_(x*L2E));
}

// ---------------- grid barrier (128 co-resident blocks) ----------------
__device__ __forceinline__ void gridbar(){
    __syncthreads();
    if (threadIdx.x == 0){
        __threadfence();
        unsigned gen = g_bar_gen;
        unsigned old = atomicAdd(&g_bar_cnt, 1u);
        if (old == gridDim.x - 1u){
            g_bar_cnt = 0u;
            __threadfence();
            g_bar_gen = gen + 1u;
        } else {
            while (g_bar_gen == gen) __nanosleep(20);
        }
        __threadfence();
    }
    __syncthreads();
}

// ---------------- megakernel ----------------
__global__ void __launch_bounds__(NTH,1) k_mega(
    const float* __restrict__ x,
    const float* __restrict__ conv_re_w, const float* __restrict__ conv_re_b,
    const float* __restrict__ conv_im_w, const float* __restrict__ conv_im_b,
    const float* __restrict__ pos,
    const float* __restrict__ bn_gamma, const float* __restrict__ bn_beta,
    const float* __restrict__ rms_w,
    const float* __restrict__ in_proj_w,
    const float* __restrict__ conv1d_w, const float* __restrict__ conv1d_b,
    const float* __restrict__ x_proj_w,
    const float* __restrict__ dt_proj_w, const float* __restrict__ dt_proj_b,
    const float* __restrict__ A_log,  const float* __restrict__ Dp,
    const float* __restrict__ out_proj_w,
    const float* __restrict__ fc_w, const float* __restrict__ fc_b,
    float* __restrict__ out)
{
    extern __shared__ float sm[];
    float* sxc  = sm;                       // SEGL*ED
    float* ssz  = sm + SEGL*ED;             // SEGL*ED
    float* sdbl = sm + 2*SEGL*ED;           // SEGL*DBLW
    const int NB  = gridDim.x;              // 128
    const int bid = blockIdx.x;
    const int tid = threadIdx.x;
    const int gsz = NB*NTH;
    const int gtid = bid*NTH + tid;
    const int warp = tid >> 5, lane = tid & 31;

    const int seg_b = bid >> 2;             // batch
    const int seg_s = bid & 3;              // quarter
    const int rowbase = bid*SEGL;           // == seg_b*LP + seg_s*SEGL

    // ===== phase 0: A2, conv-w transpose, front-end, zero BN accum =====
    for (int i = gtid; i < NL*ED*NS; i += gsz) g_A2[i] = -expf(A_log[i]) * L2E;
    for (int i = gtid; i < NL*ED; i += gsz){
        int layer = i / ED, e = i % ED;
        const float* wp = conv1d_w + i*3;
        float* dst = g_cwT + layer*4*ED;
        dst[0*ED+e] = wp[0];
        dst[1*ED+e] = wp[1];
        dst[2*ED+e] = wp[2];
        dst[3*ED+e] = conv1d_b[i];
    }
    if (gtid < 2*DM) g_bns[gtid] = 0.f;
    for (int idx = gtid; idx < ROWS*DM; idx += gsz){
        int row = idx / DM, o = idx % DM;
        int b = row / LP, l = row % LP;
        const float* xr = x + b*(2*LP*PP) + l*PP;
        const float* xi = xr + LP*PP;
        float acc;
        if (o < 6){
            acc = conv_re_b[o] - conv_im_b[o];
            const float* w1 = conv_re_w + o*PP; const float* w2 = conv_im_w + o*PP;
            #pragma unroll 10
            for (int k=0;k<PP;k++) acc += xr[k]*w1[k] - xi[k]*w2[k];
        } else {
            int o6 = o-6;
            acc = conv_re_b[o6] + conv_im_b[o6];
            const float* w1 = conv_re_w + o6*PP; const float* w2 = conv_im_w + o6*PP;
            #pragma unroll 10
            for (int k=0;k<PP;k++) acc += xi[k]*w1[k] + xr[k]*w2[k];
        }
        g_h[idx] = acc + pos[l*DM + o];
    }
    gridbar();

    // ===== BN sums =====
    {
        float ls[DM], lq[DM];
        #pragma unroll
        for(int c=0;c<DM;c++){ ls[c]=0.f; lq[c]=0.f; }
        for (int j = gtid; j < ROWS; j += gsz){
            #pragma unroll
            for(int c=0;c<DM;c++){ float v=g_h[j*DM+c]; ls[c]+=v; lq[c]+=v*v; }
        }
        #pragma unroll
        for(int c=0;c<DM;c++){
            float a=ls[c], q=lq[c];
            for(int off=16;off>0;off>>=1){
                a+=__shfl_down_sync(0xffffffffu,a,off);
                q+=__shfl_down_sync(0xffffffffu,q,off);
            }
            if (lane==0 && (a!=0.f || q!=0.f)){
                atomicAdd(&g_bns[c], a);
                atomicAdd(&g_bns[DM+c], q);
            }
        }
    }
    gridbar();

    // ===== BN apply + silu =====
    {
        if (tid < DM){
            float mu  = g_bns[tid]*(1.0f/ROWS);
            float var = g_bns[DM+tid]*(1.0f/ROWS) - mu*mu;
            float sc  = rsqrtf(var+1e-6f)*bn_gamma[tid];
            sm[tid]    = sc;
            sm[DM+tid] = bn_beta[tid] - mu*sc;
        }
        __syncthreads();
        for (int idx = gtid; idx < ROWS*DM; idx += gsz){
            int c = idx % DM;
            float v = g_h[idx]*sm[c] + sm[DM+c];
            g_h[idx] = siluf_(v);
        }
        __syncthreads();
    }
    gridbar();

    // ===== layers =====
    for (int layer = 0; layer < NL; layer++){
        // ---- rmsnorm + in_proj for this block's 24 rows; 2 cols/thread ----
        {
            float* su   = sxc;             // 24*DM
            float* srms = sxc + 320;
            const float* Wl  = in_proj_w + layer*XZW*DM;
            const float* rwl = rms_w + layer*DM;
            if (tid < SEGL*DM) su[tid] = g_h[rowbase*DM + tid];
            __syncthreads();
            if (tid < SEGL){
                float s=0.f;
                #pragma unroll
                for(int d=0;d<DM;d++){ float v=su[tid*DM+d]; s+=v*v; }
                srms[tid] = rsqrtf(s*(1.0f/DM)+1e-5f);
            }
            __syncthreads();
            float uv = 0.f;
            if (tid < SEGL*DM) uv = su[tid]*srms[tid/DM]*rwl[tid%DM];
            __syncthreads();
            if (tid < SEGL*DM) su[tid] = uv;
            __syncthreads();
            float w[2][DM];
            #pragma unroll
            for(int j=0;j<2;j++){
                const float* wp = Wl + (tid + NTH*j)*DM;
                #pragma unroll
                for(int d=0;d<DM;d++) w[j][d]=wp[d];
            }
            for (int r=0;r<SEGL;r++){
                float u[DM];
                #pragma unroll
                for(int d=0;d<DM;d++) u[d]=su[r*DM+d];
                #pragma unroll
                for(int j=0;j<2;j++){
                    float acc=0.f;
                    #pragma unroll
                    for(int d=0;d<DM;d++) acc += u[d]*w[j][d];
                    g_xz[(rowbase+r)*XZW + tid + NTH*j] = acc;
                }
            }
        }
        gridbar();   // xz halo crosses blocks

        // ---- conv(3)+silu + silu(z) + x_proj: warp per row, float4 ----
        {
            int row = rowbase + warp;
            int l0 = row % LP;
            const float* cwT = g_cwT + layer*4*ED;
            const float* Wx  = x_proj_w + layer*DBLW*ED;
            float part[DBLW];
            #pragma unroll
            for(int t=0;t<DBLW;t++) part[t]=0.f;
            #pragma unroll
            for (int c=0;c<6;c++){
                int e0 = c*128 + lane*4;
                float4 w0 = *(const float4*)(cwT + 0*ED + e0);
                float4 w1 = *(const float4*)(cwT + 1*ED + e0);
                float4 w2 = *(const float4*)(cwT + 2*ED + e0);
                float4 b4 = *(const float4*)(cwT + 3*ED + e0);
                float4 z4 = {0,0,0,0}, m1 = {0,0,0,0}, m2 = {0,0,0,0};
                if (l0>=2) m2 = *(const float4*)(g_xz + (row-2)*XZW + e0);
                if (l0>=1) m1 = *(const float4*)(g_xz + (row-1)*XZW + e0);
                float4 x0 = *(const float4*)(g_xz + row*XZW + e0);
                z4 = *(const float4*)(g_xz + row*XZW + ED + e0);
                float4 xc4;
                xc4.x = siluf_(b4.x + w0.x*m2.x + w1.x*m1.x + w2.x*x0.x);
                xc4.y = siluf_(b4.y + w0.y*m2.y + w1.y*m1.y + w2.y*x0.y);
                xc4.z = siluf_(b4.z + w0.z*m2.z + w1.z*m1.z + w2.z*x0.z);
                xc4.w = siluf_(b4.w + w0.w*m2.w + w1.w*m1.w + w2.w*x0.w);
                *(float4*)(sxc + warp*ED + e0) = xc4;
                z4.x = siluf_(z4.x); z4.y = siluf_(z4.y);
                z4.z = siluf_(z4.z); z4.w = siluf_(z4.w);
                *(float4*)(ssz + warp*ED + e0) = z4;
                #pragma unroll
                for(int t=0;t<DBLW;t++){
                    float4 wt = __ldg((const float4*)(Wx + t*ED + e0));
                    part[t] += wt.x*xc4.x + wt.y*xc4.y + wt.z*xc4.z + wt.w*xc4.w;
                }
            }
            #pragma unroll
            for(int t=0;t<DBLW;t++){
                float v = part[t];
                for(int off=16;off>0;off>>=1) v += __shfl_down_sync(0xffffffffu, v, off);
                if (lane==0) sdbl[warp*DBLW + t] = v;
            }
        }
        __syncthreads();

        // ---- scan stage A: transfer (P,q) for segments 0..2 ----
        if (seg_s < 3){
            int e = tid;
            float a2[NS];
            const float* ap = g_A2 + (layer*ED + e)*NS;
            #pragma unroll
            for(int n=0;n<NS;n++) a2[n]=ap[n];
            bool geo = true;
            #pragma unroll
            for(int n=1;n<NS;n++)
                geo = geo && (fabsf(a2[n] - (float)(n+1)*a2[0]) <= 1e-4f*fabsf(a2[n]));
            float dw = dt_proj_w[layer*ED + e];
            float db = dt_proj_b[layer*ED + e];
            float st[NS], sumd = 0.f;
            #pragma unroll
            for(int n=0;n<NS;n++) st[n]=0.f;
            for (int li=0; li<SEGL; li++){
                float xc = sxc[li*ED + e];
                const float* dl = sdbl + li*DBLW;
                float delta = softplusf_(dl[0]*dw + db);
                sumd += delta;
                float dx = delta * xc;
                float p = ex2f_(delta * a2[0]);
                float dan = 1.f;
                #pragma unroll
                for(int n=0;n<NS;n++){
                    if (geo) dan *= p;
                    else     dan = ex2f_(delta * a2[n]);
                    st[n] = dan*st[n] + dx*dl[1+n];
                }
            }
            int base = ((seg_s*BSZ + seg_b)*NS)*ED + e;
            #pragma unroll
            for(int n=0;n<NS;n++){
                g_P[base + n*ED] = ex2f_(a2[n]*sumd);
                g_q[base + n*ED] = st[n];
            }
        }
        gridbar();   // P/q exchange

        // ---- scan stage C + gate + out_proj (same segment, smem-resident) ----
        {
            int e = tid;
            float a2[NS];
            const float* ap = g_A2 + (layer*ED + e)*NS;
            #pragma unroll
            for(int n=0;n<NS;n++) a2[n]=ap[n];
            bool geo = true;
            #pragma unroll
            for(int n=1;n<NS;n++)
                geo = geo && (fabsf(a2[n] - (float)(n+1)*a2[0]) <= 1e-4f*fabsf(a2[n]));
            float dw = dt_proj_w[layer*ED + e];
            float db = dt_proj_b[layer*ED + e];
            float Dv = Dp [layer*ED + e];
            float hn[NS];
            #pragma unroll
            for(int n=0;n<NS;n++) hn[n]=0.f;
            for (int sp=0; sp<seg_s; sp++){
                int base = ((sp*BSZ + seg_b)*NS)*ED + e;
                #pragma unroll
                for(int n=0;n<NS;n++)
                    hn[n] = g_P[base + n*ED]*hn[n] + g_q[base + n*ED];
            }
            for (int li=0; li<SEGL; li++){
                const float* dl = sdbl + li*DBLW;
                float xc = sxc[li*ED + e];
                float delta = softplusf_(dl[0]*dw + db);
                float dx = delta * xc;
                float y  = Dv * xc;
                float p = ex2f_(delta * a2[0]);
                float dan = 1.f;
                #pragma unroll
                for(int n=0;n<NS;n++){
                    if (geo) dan *= p;
                    else     dan = ex2f_(delta * a2[n]);
                    hn[n] = dan*hn[n] + dx*dl[1+n];
                    y += hn[n]*dl[9+n];
                }
                sxc[li*ED + e] = y * ssz[li*ED + e];   // gated y replaces xc
            }
        }
        __syncthreads();

        // ---- out_proj: warp per row over smem y, float4 weights ----
        {
            int row = rowbase + warp;
            const float* Wo = out_proj_w + layer*DM*ED;
            float pd[DM];
            #pragma unroll
            for(int d=0;d<DM;d++) pd[d]=0.f;
            #pragma unroll
            for (int c=0;c<6;c++){
                int e0 = c*128 + lane*4;
                float4 y4 = *(const float4*)(sxc + warp*ED + e0);
                #pragma unroll
                for(int d=0;d<DM;d++){
                    float4 wd4 = __ldg((const float4*)(Wo + d*ED + e0));
                    pd[d] += wd4.x*y4.x + wd4.y*y4.y + wd4.z*y4.z + wd4.w*y4.w;
                }
            }
            #pragma unroll
            for(int d=0;d<DM;d++){
                float v = pd[d];
                for(int off=16;off>0;off>>=1) v += __shfl_down_sync(0xffffffffu, v, off);
                if (lane==0) g_h[row*DM + d] += v;
            }
        }
        __syncthreads();   // g_h rows owned by this block; sxc reused next iter
    }
    gridbar();

    // ===== final: mean over L + FC + ReLU =====
    {
        float* m = sm;
        for (int b = bid; b < BSZ; b += NB){
            if (tid < DM){
                float s=0.f;
                for(int l=0;l<LP;l++) s += g_h[(b*LP+l)*DM + tid];
                m[tid]=s*(1.0f/LP);
            }
            __syncthreads();
            if (tid < EMB){
                float acc = fc_b[tid];
                #pragma unroll
                for(int d=0;d<DM;d++) acc += m[d]*fc_w[tid*DM+d];
                out[b*EMB+tid] = fmaxf(acc,0.0f);
            }
            __syncthreads();
        }
    }
}

// ---------------- launch ----------------
extern "C" void kernel_launch(void* const* d_in, const int* in_sizes, int n_in,
                              void* d_out, int out_size){
    const float* x          = (const float*)d_in[0];
    const float* conv_re_w  = (const float*)d_in[1];
    const float* conv_re_b  = (const float*)d_in[2];
    const float* conv_im_w  = (const float*)d_in[3];
    const float* conv_im_b  = (const float*)d_in[4];
    const float* pos        = (const float*)d_in[5];
    const float* bn_gamma   = (const float*)d_in[6];
    const float* bn_beta    = (const float*)d_in[7];
    const float* rms_w      = (const float*)d_in[8];
    const float* in_proj_w  = (const float*)d_in[9];
    const float* conv1d_w   = (const float*)d_in[10];
    const float* conv1d_b   = (const float*)d_in[11];
    const float* x_proj_w   = (const float*)d_in[12];
    const float* dt_proj_w  = (const float*)d_in[13];
    const float* dt_proj_b  = (const float*)d_in[14];
    const float* A_log      = (const float*)d_in[15];
    const float* Dp         = (const float*)d_in[16];
    const float* out_proj_w = (const float*)d_in[17];
    const float* fc_w       = (const float*)d_in[18];
    const float* fc_b       = (const float*)d_in[19];
    float* out = (float*)d_out;

    size_t dynbytes = (size_t)DYNF * sizeof(float);
    cudaFuncSetAttribute(k_mega, cudaFuncAttributeMaxDynamicSharedMemorySize, (int)dynbytes);

    k_mega<<<NBLK, NTH, dynbytes>>>(x, conv_re_w, conv_re_b, conv_im_w, conv_im_b, pos,
                         bn_gamma, bn_beta, rms_w, in_proj_w, conv1d_w, conv1d_b,
                         x_proj_w, dt_proj_w, dt_proj_b, A_log, Dp, out_proj_w,
                         fc_w, fc_b, out);
}

// round 10
// speedup vs baseline: 2.7257x; 1.0112x over previous
#include <cuda_runtime.h>

#define BSZ 32
#define LP 96
#define DM 12
#define ED 768
#define NS 8
#define NL 10
#define EMB 256
#define PP 50
#define ROWS (BSZ*LP)      // 3072
#define XZW (2*ED)         // 1536
#define DBLW 17
#define DBLS 20            // padded smem stride for dbl rows
#define NTH 768
#define NBLK 128
#define SEGL 24

// smem layout (floats)
#define S_XC   0
#define S_DL   (SEGL*ED)                 // 18432
#define S_DB   (2*SEGL*ED)               // 36864
#define S_TMP  (2*SEGL*ED + SEGL*DBLS)   // 37344
#define DYNF   (S_TMP + 2*SEGL*DBLW + 32)

// ---------------- scratch ----------------
__device__ __align__(16) float g_h[ROWS*DM];
__device__ __align__(16) float g_xz[ROWS*XZW];
__device__ __align__(16) float g_P[3*BSZ*NS*ED];
__device__ __align__(16) float g_q[3*BSZ*NS*ED];
__device__ __align__(16) float g_A2[NL*ED*NS];
__device__ __align__(16) float g_cwT[NL*4*ED];   // [layer][{w0,w1,w2,bias}][e]
__device__ float g_bns[2*DM];
__device__ volatile unsigned g_bar_gen;
__device__ unsigned g_bar_cnt;

// ---------------- fast math ----------------
__device__ __forceinline__ float ex2f_(float x){ float y; asm("ex2.approx.f32 %0, %1;":"=f"(y):"f"(x)); return y; }
__device__ __forceinline__ float lg2f_(float x){ float y; asm("lg2.approx.f32 %0, %1;":"=f"(y):"f"(x)); return y; }
__device__ __forceinline__ float rcpf_(float x){ float y; asm("rcp.approx.f32 %0, %1;":"=f"(y):"f"(x)); return y; }
#define L2E 1.4426950408889634f
#define LN2 0.6931471805599453f
__device__ __forceinline__ float sigmoidf_(float x){ return rcpf_(1.0f + ex2f_(-x*L2E)); }
__device__ __forceinline__ float siluf_(float x){ return x * sigmoidf_(x); }
__device__ __forceinline__ float softplusf_(float x){
    return (x > 20.0f) ? x : LN2*lg2f_(1.0f + ex2f_(x*L2E));
}

// ---------------- grid barrier (128 co-resident blocks) ----------------
__device__ __forceinline__ void gridbar(){
    __syncthreads();
    if (threadIdx.x == 0){
        __threadfence();
        unsigned gen = g_bar_gen;
        unsigned old = atomicAdd(&g_bar_cnt, 1u);
        if (old == gridDim.x - 1u){
            g_bar_cnt = 0u;
            __threadfence();
            g_bar_gen = gen + 1u;
        } else {
            while (g_bar_gen == gen) __nanosleep(20);
        }
        __threadfence();
    }
    __syncthreads();
}

// ---------------- megakernel ----------------
__global__ void __launch_bounds__(NTH,1) k_mega(
    const float* __restrict__ x,
    const float* __restrict__ conv_re_w, const float* __restrict__ conv_re_b,
    const float* __restrict__ conv_im_w, const float* __restrict__ conv_im_b,
    const float* __restrict__ pos,
    const float* __restrict__ bn_gamma, const float* __restrict__ bn_beta,
    const float* __restrict__ rms_w,
    const float* __restrict__ in_proj_w,
    const float* __restrict__ conv1d_w, const float* __restrict__ conv1d_b,
    const float* __restrict__ x_proj_w,
    const float* __restrict__ dt_proj_w, const float* __restrict__ dt_proj_b,
    const float* __restrict__ A_log,  const float* __restrict__ Dp,
    const float* __restrict__ out_proj_w,
    const float* __restrict__ fc_w, const float* __restrict__ fc_b,
    float* __restrict__ out)
{
    extern __shared__ float sm[];
    float* sxc  = sm + S_XC;
    float* sdl  = sm + S_DL;
    float* sdb  = sm + S_DB;
    float* stmp = sm + S_TMP;
    const int NB  = gridDim.x;              // 128
    const int bid = blockIdx.x;
    const int tid = threadIdx.x;
    const int gsz = NB*NTH;
    const int gtid = bid*NTH + tid;
    const int warp = tid >> 5, lane = tid & 31;

    const int seg_b = bid >> 2;             // batch
    const int seg_s = bid & 3;              // quarter
    const int rowbase = bid*SEGL;

    // ===== phase 0: A2, conv-w transpose, front-end, zero BN accum =====
    for (int i = gtid; i < NL*ED*NS; i += gsz) g_A2[i] = -expf(A_log[i]) * L2E;
    for (int i = gtid; i < NL*ED; i += gsz){
        int layer = i / ED, e = i % ED;
        const float* wp = conv1d_w + i*3;
        float* dst = g_cwT + layer*4*ED;
        dst[0*ED+e] = wp[0];
        dst[1*ED+e] = wp[1];
        dst[2*ED+e] = wp[2];
        dst[3*ED+e] = conv1d_b[i];
    }
    if (gtid < 2*DM) g_bns[gtid] = 0.f;
    for (int idx = gtid; idx < ROWS*DM; idx += gsz){
        int row = idx / DM, o = idx % DM;
        int b = row / LP, l = row % LP;
        const float* xr = x + b*(2*LP*PP) + l*PP;
        const float* xi = xr + LP*PP;
        float acc;
        if (o < 6){
            acc = conv_re_b[o] - conv_im_b[o];
            const float* w1 = conv_re_w + o*PP; const float* w2 = conv_im_w + o*PP;
            #pragma unroll 10
            for (int k=0;k<PP;k++) acc += xr[k]*w1[k] - xi[k]*w2[k];
        } else {
            int o6 = o-6;
            acc = conv_re_b[o6] + conv_im_b[o6];
            const float* w1 = conv_re_w + o6*PP; const float* w2 = conv_im_w + o6*PP;
            #pragma unroll 10
            for (int k=0;k<PP;k++) acc += xi[k]*w1[k] + xr[k]*w2[k];
        }
        g_h[idx] = acc + pos[l*DM + o];
    }
    gridbar();

    // ===== BN sums =====
    {
        float ls[DM], lq[DM];
        #pragma unroll
        for(int c=0;c<DM;c++){ ls[c]=0.f; lq[c]=0.f; }
        for (int j = gtid; j < ROWS; j += gsz){
            #pragma unroll
            for(int c=0;c<DM;c++){ float v=g_h[j*DM+c]; ls[c]+=v; lq[c]+=v*v; }
        }
        #pragma unroll
        for(int c=0;c<DM;c++){
            float a=ls[c], q=lq[c];
            for(int off=16;off>0;off>>=1){
                a+=__shfl_down_sync(0xffffffffu,a,off);
                q+=__shfl_down_sync(0xffffffffu,q,off);
            }
            if (lane==0 && (a!=0.f || q!=0.f)){
                atomicAdd(&g_bns[c], a);
                atomicAdd(&g_bns[DM+c], q);
            }
        }
    }
    gridbar();

    // ===== BN apply + silu =====
    {
        if (tid < DM){
            float mu  = g_bns[tid]*(1.0f/ROWS);
            float var = g_bns[DM+tid]*(1.0f/ROWS) - mu*mu;
            float sc  = rsqrtf(var+1e-6f)*bn_gamma[tid];
            sm[tid]    = sc;
            sm[DM+tid] = bn_beta[tid] - mu*sc;
        }
        __syncthreads();
        for (int idx = gtid; idx < ROWS*DM; idx += gsz){
            int c = idx % DM;
            float v = g_h[idx]*sm[c] + sm[DM+c];
            g_h[idx] = siluf_(v);
        }
        __syncthreads();
    }
    gridbar();

    // ===== layers =====
    for (int layer = 0; layer < NL; layer++){
        // ---- rmsnorm + in_proj for this block's 24 rows; 2 cols/thread ----
        {
            float* su   = sxc;             // 24*DM scratch (before cvxp writes)
            float* srms = sxc + 320;
            const float* Wl  = in_proj_w + layer*XZW*DM;
            const float* rwl = rms_w + layer*DM;
            if (tid < SEGL*DM) su[tid] = g_h[rowbase*DM + tid];
            __syncthreads();
            if (tid < SEGL){
                float s=0.f;
                #pragma unroll
                for(int d=0;d<DM;d++){ float v=su[tid*DM+d]; s+=v*v; }
                srms[tid] = rsqrtf(s*(1.0f/DM)+1e-5f);
            }
            __syncthreads();
            float uv = 0.f;
            if (tid < SEGL*DM) uv = su[tid]*srms[tid/DM]*rwl[tid%DM];
            __syncthreads();
            if (tid < SEGL*DM) su[tid] = uv;
            __syncthreads();
            float w[2][DM];
            #pragma unroll
            for(int j=0;j<2;j++){
                const float* wp = Wl + (tid + NTH*j)*DM;
                #pragma unroll
                for(int d=0;d<DM;d++) w[j][d]=wp[d];
            }
            for (int r=0;r<SEGL;r++){
                float u[DM];
                #pragma unroll
                for(int d=0;d<DM;d++) u[d]=su[r*DM+d];
                #pragma unroll
                for(int j=0;j<2;j++){
                    float acc=0.f;
                    #pragma unroll
                    for(int d=0;d<DM;d++) acc += u[d]*w[j][d];
                    g_xz[(rowbase+r)*XZW + tid + NTH*j] = acc;
                }
            }
        }
        gridbar();   // xz halo crosses blocks

        // ---- conv(3)+silu + x_proj: warp = (row-pair, e-half), weights reused x2 ----
        {
            const int pair  = warp >> 1;       // 0..11
            const int split = warp & 1;        // 0..1
            const int r0    = pair*2;
            const int grow0 = rowbase + r0;
            const int l0    = grow0 % LP;
            const float* cwT = g_cwT + layer*4*ED;
            const float* Wx  = x_proj_w + layer*DBLW*ED;
            float part[2][DBLW];
            #pragma unroll
            for(int r=0;r<2;r++)
                #pragma unroll
                for(int t=0;t<DBLW;t++) part[r][t]=0.f;
            #pragma unroll
            for (int c=0;c<3;c++){
                int e0 = split*384 + c*128 + lane*4;
                float4 w0 = __ldg((const float4*)(cwT + 0*ED + e0));
                float4 w1 = __ldg((const float4*)(cwT + 1*ED + e0));
                float4 w2 = __ldg((const float4*)(cwT + 2*ED + e0));
                float4 b4 = __ldg((const float4*)(cwT + 3*ED + e0));
                float4 xm2 = {0,0,0,0}, xm1 = {0,0,0,0};
                if (l0>=2) xm2 = *(const float4*)(g_xz + (grow0-2)*XZW + e0);
                if (l0>=1) xm1 = *(const float4*)(g_xz + (grow0-1)*XZW + e0);
                float4 x0 = *(const float4*)(g_xz + grow0*XZW + e0);
                float4 x1 = *(const float4*)(g_xz + (grow0+1)*XZW + e0);
                float4 xc0, xc1;
                xc0.x = siluf_(b4.x + w0.x*xm2.x + w1.x*xm1.x + w2.x*x0.x);
                xc0.y = siluf_(b4.y + w0.y*xm2.y + w1.y*xm1.y + w2.y*x0.y);
                xc0.z = siluf_(b4.z + w0.z*xm2.z + w1.z*xm1.z + w2.z*x0.z);
                xc0.w = siluf_(b4.w + w0.w*xm2.w + w1.w*xm1.w + w2.w*x0.w);
                xc1.x = siluf_(b4.x + w0.x*xm1.x + w1.x*x0.x + w2.x*x1.x);
                xc1.y = siluf_(b4.y + w0.y*xm1.y + w1.y*x0.y + w2.y*x1.y);
                xc1.z = siluf_(b4.z + w0.z*xm1.z + w1.z*x0.z + w2.z*x1.z);
                xc1.w = siluf_(b4.w + w0.w*xm1.w + w1.w*x0.w + w2.w*x1.w);
                *(float4*)(sxc + r0*ED + e0)     = xc0;
                *(float4*)(sxc + (r0+1)*ED + e0) = xc1;
                #pragma unroll
                for(int t=0;t<DBLW;t++){
                    float4 wt = __ldg((const float4*)(Wx + t*ED + e0));
                    part[0][t] += wt.x*xc0.x + wt.y*xc0.y + wt.z*xc0.z + wt.w*xc0.w;
                    part[1][t] += wt.x*xc1.x + wt.y*xc1.y + wt.z*xc1.z + wt.w*xc1.w;
                }
            }
            #pragma unroll
            for(int r=0;r<2;r++)
                #pragma unroll
                for(int t=0;t<DBLW;t++){
                    float v = part[r][t];
                    for(int off=16;off>0;off>>=1) v += __shfl_down_sync(0xffffffffu, v, off);
                    if (lane==0) stmp[(split*SEGL + r0 + r)*DBLW + t] = v;
                }
        }
        __syncthreads();
        // combine e-halves into padded sdb rows: [B0..7 | C0..7 | d0]
        for (int idx = tid; idx < SEGL*DBLW; idx += NTH){
            int row = idx / DBLW, t = idx % DBLW;
            float v = stmp[row*DBLW + t] + stmp[(SEGL+row)*DBLW + t];
            sdb[row*DBLS + (t==0 ? 16 : (t-1))] = v;
        }
        __syncthreads();
        // delta pass: s_delta[row][e]
        {
            float dw = dt_proj_w[layer*ED + tid];
            float db = dt_proj_b[layer*ED + tid];
            #pragma unroll 4
            for (int r=0;r<SEGL;r++){
                float d0 = sdb[r*DBLS + 16];
                sdl[r*ED + tid] = softplusf_(d0*dw + db);
            }
        }
        __syncthreads();

        // ---- scan stage A: transfer (P,q) for segments 0..2 ----
        if (seg_s < 3){
            int e = tid;
            float a2[NS];
            const float* ap = g_A2 + (layer*ED + e)*NS;
            #pragma unroll
            for(int n=0;n<NS;n++) a2[n]=ap[n];
            bool geo = true;
            #pragma unroll
            for(int n=1;n<NS;n++)
                geo = geo && (fabsf(a2[n] - (float)(n+1)*a2[0]) <= 1e-4f*fabsf(a2[n]));
            float st[NS], sumd = 0.f;
            #pragma unroll
            for(int n=0;n<NS;n++) st[n]=0.f;
            for (int li=0; li<SEGL; li++){
                float delta = sdl[li*ED + e];
                float xc    = sxc[li*ED + e];
                float dx = delta * xc;
                float4 B0 = *(const float4*)(sdb + li*DBLS);
                float4 B1 = *(const float4*)(sdb + li*DBLS + 4);
                float Bv[NS] = {B0.x,B0.y,B0.z,B0.w,B1.x,B1.y,B1.z,B1.w};
                float p = ex2f_(delta * a2[0]);
                float dan = 1.f;
                #pragma unroll
                for(int n=0;n<NS;n++){
                    if (geo) dan *= p;
                    else     dan = ex2f_(delta * a2[n]);
                    st[n] = dan*st[n] + dx*Bv[n];
                }
                sumd += delta;
            }
            int base = ((seg_s*BSZ + seg_b)*NS)*ED + e;
            #pragma unroll
            for(int n=0;n<NS;n++){
                g_P[base + n*ED] = ex2f_(a2[n]*sumd);
                g_q[base + n*ED] = st[n];
            }
        }
        gridbar();   // P/q exchange

        // ---- scan stage C + gate (y stays in sxc) ----
        {
            int e = tid;
            float a2[NS];
            const float* ap = g_A2 + (layer*ED + e)*NS;
            #pragma unroll
            for(int n=0;n<NS;n++) a2[n]=ap[n];
            bool geo = true;
            #pragma unroll
            for(int n=1;n<NS;n++)
                geo = geo && (fabsf(a2[n] - (float)(n+1)*a2[0]) <= 1e-4f*fabsf(a2[n]));
            float Dv = Dp[layer*ED + e];
            float hn[NS];
            #pragma unroll
            for(int n=0;n<NS;n++) hn[n]=0.f;
            for (int sp=0; sp<seg_s; sp++){
                int base = ((sp*BSZ + seg_b)*NS)*ED + e;
                #pragma unroll
                for(int n=0;n<NS;n++)
                    hn[n] = g_P[base + n*ED]*hn[n] + g_q[base + n*ED];
            }
            float z_n = g_xz[rowbase*XZW + ED + e];
            for (int li=0; li<SEGL; li++){
                float z = z_n;
                if (li < SEGL-1) z_n = g_xz[(rowbase+li+1)*XZW + ED + e];
                float delta = sdl[li*ED + e];
                float xc    = sxc[li*ED + e];
                float dx = delta * xc;
                float4 B0 = *(const float4*)(sdb + li*DBLS);
                float4 B1 = *(const float4*)(sdb + li*DBLS + 4);
                float4 C0 = *(const float4*)(sdb + li*DBLS + 8);
                float4 C1 = *(const float4*)(sdb + li*DBLS + 12);
                float Bv[NS] = {B0.x,B0.y,B0.z,B0.w,B1.x,B1.y,B1.z,B1.w};
                float Cv[NS] = {C0.x,C0.y,C0.z,C0.w,C1.x,C1.y,C1.z,C1.w};
                float y = Dv * xc;
                float p = ex2f_(delta * a2[0]);
                float dan = 1.f;
                #pragma unroll
                for(int n=0;n<NS;n++){
                    if (geo) dan *= p;
                    else     dan = ex2f_(delta * a2[n]);
                    hn[n] = dan*hn[n] + dx*Bv[n];
                    y += hn[n]*Cv[n];
                }
                sxc[li*ED + e] = y * siluf_(z);
            }
        }
        __syncthreads();

        // ---- out_proj: warp = (row-pair, e-half), weights reused x2 ----
        {
            const int pair  = warp >> 1;
            const int split = warp & 1;
            const int r0    = pair*2;
            const float* Wo = out_proj_w + layer*DM*ED;
            float pd[2][DM];
            #pragma unroll
            for(int r=0;r<2;r++)
                #pragma unroll
                for(int d=0;d<DM;d++) pd[r][d]=0.f;
            #pragma unroll
            for (int c=0;c<3;c++){
                int e0 = split*384 + c*128 + lane*4;
                float4 y0 = *(const float4*)(sxc + r0*ED + e0);
                float4 y1 = *(const float4*)(sxc + (r0+1)*ED + e0);
                #pragma unroll
                for(int d=0;d<DM;d++){
                    float4 wd4 = __ldg((const float4*)(Wo + d*ED + e0));
                    pd[0][d] += wd4.x*y0.x + wd4.y*y0.y + wd4.z*y0.z + wd4.w*y0.w;
                    pd[1][d] += wd4.x*y1.x + wd4.y*y1.y + wd4.z*y1.z + wd4.w*y1.w;
                }
            }
            #pragma unroll
            for(int r=0;r<2;r++)
                #pragma unroll
                for(int d=0;d<DM;d++){
                    float v = pd[r][d];
                    for(int off=16;off>0;off>>=1) v += __shfl_down_sync(0xffffffffu, v, off);
                    if (lane==0) stmp[(split*SEGL + r0 + r)*DM + d] = v;
                }
        }
        __syncthreads();
        for (int idx = tid; idx < SEGL*DM; idx += NTH){
            int row = idx / DM, d = idx % DM;
            g_h[(rowbase+row)*DM + d] += stmp[row*DM + d] + stmp[(SEGL+row)*DM + d];
        }
        __syncthreads();   // g_h rows owned by this block
    }
    gridbar();

    // ===== final: mean over L + FC + ReLU =====
    {
        float* m = sm;
        for (int b = bid; b < BSZ; b += NB){
            if (tid < DM){
                float s=0.f;
                for(int l=0;l<LP;l++) s += g_h[(b*LP+l)*DM + tid];
                m[tid]=s*(1.0f/LP);
            }
            __syncthreads();
            if (tid < EMB){
                float acc = fc_b[tid];
                #pragma unroll
                for(int d=0;d<DM;d++) acc += m[d]*fc_w[tid*DM+d];
                out[b*EMB+tid] = fmaxf(acc,0.0f);
            }
            __syncthreads();
        }
    }
}

// ---------------- launch ----------------
extern "C" void kernel_launch(void* const* d_in, const int* in_sizes, int n_in,
                              void* d_out, int out_size){
    const float* x          = (const float*)d_in[0];
    const float* conv_re_w  = (const float*)d_in[1];
    const float* conv_re_b  = (const float*)d_in[2];
    const float* conv_im_w  = (const float*)d_in[3];
    const float* conv_im_b  = (const float*)d_in[4];
    const float* pos        = (const float*)d_in[5];
    const float* bn_gamma   = (const float*)d_in[6];
    const float* bn_beta    = (const float*)d_in[7];
    const float* rms_w      = (const float*)d_in[8];
    const float* in_proj_w  = (const float*)d_in[9];
    const float* conv1d_w   = (const float*)d_in[10];
    const float* conv1d_b   = (const float*)d_in[11];
    const float* x_proj_w   = (const float*)d_in[12];
    const float* dt_proj_w  = (const float*)d_in[13];
    const float* dt_proj_b  = (const float*)d_in[14];
    const float* A_log      = (const float*)d_in[15];
    const float* Dp         = (const float*)d_in[16];
    const float* out_proj_w = (const float*)d_in[17];
    const float* fc_w       = (const float*)d_in[18];
    const float* fc_b       = (const float*)d_in[19];
    float* out = (float*)d_out;

    size_t dynbytes = (size_t)DYNF * sizeof(float);
    cudaFuncSetAttribute(k_mega, cudaFuncAttributeMaxDynamicSharedMemorySize, (int)dynbytes);

    k_mega<<<NBLK, NTH, dynbytes>>>(x, conv_re_w, conv_re_b, conv_im_w, conv_im_b, pos,
                         bn_gamma, bn_beta, rms_w, in_proj_w, conv1d_w, conv1d_b,
                         x_proj_w, dt_proj_w, dt_proj_b, A_log, Dp, out_proj_w,
                         fc_w, fc_b, out);
}

// round 11
// speedup vs baseline: 2.9928x; 1.0980x over previous
#include <cuda_runtime.h>

#define BSZ 32
#define LP 96
#define DM 12
#define ED 768
#define NS 8
#define NL 10
#define EMB 256
#define PP 50
#define ROWS (BSZ*LP)      // 3072
#define XZW (2*ED)         // 1536
#define DBLW 17
#define DBLS 20
#define NTH 768
#define NBLK 128
#define SEGL 24
#define PQSTRIDE (3*BSZ*NS*ED)

// smem layout (floats)
#define S_XC   0
#define S_DL   (SEGL*ED)
#define S_DB   (2*SEGL*ED)
#define S_TMP  (2*SEGL*ED + SEGL*DBLS)
#define DYNF   (S_TMP + 2*SEGL*DBLW + 32)

// ---------------- scratch ----------------
__device__ __align__(16) float g_h[ROWS*DM];
__device__ __align__(16) float g_xz[ROWS*XZW];
__device__ __align__(16) float g_P[2*PQSTRIDE];   // parity double buffer
__device__ __align__(16) float g_q[2*PQSTRIDE];
__device__ __align__(16) float g_A2[NL*ED*NS];
__device__ __align__(16) float g_cwT[NL*4*ED];
__device__ float g_bns[2*DM];
__device__ unsigned g_xz_ready[NBLK];
__device__ unsigned g_xz_ack[NBLK];
__device__ unsigned g_pq_ready[NBLK];
__device__ unsigned g_pq_ack[NBLK];
__device__ volatile unsigned g_bar_gen;
__device__ unsigned g_bar_cnt;

// ---------------- fast math ----------------
__device__ __forceinline__ float ex2f_(float x){ float y; asm("ex2.approx.f32 %0, %1;":"=f"(y):"f"(x)); return y; }
__device__ __forceinline__ float lg2f_(float x){ float y; asm("lg2.approx.f32 %0, %1;":"=f"(y):"f"(x)); return y; }
__device__ __forceinline__ float rcpf_(float x){ float y; asm("rcp.approx.f32 %0, %1;":"=f"(y):"f"(x)); return y; }
#define L2E 1.4426950408889634f
#define LN2 0.6931471805599453f
__device__ __forceinline__ float sigmoidf_(float x){ return rcpf_(1.0f + ex2f_(-x*L2E)); }
__device__ __forceinline__ float siluf_(float x){ return x * sigmoidf_(x); }
__device__ __forceinline__ float softplusf_(float x){
    return (x > 20.0f) ? x : LN2*lg2f_(1.0f + ex2f_(x*L2E));
}

// ---------------- sync primitives ----------------
__device__ __forceinline__ void gridbar(){
    __syncthreads();
    if (threadIdx.x == 0){
        __threadfence();
        unsigned gen = g_bar_gen;
        unsigned old = atomicAdd(&g_bar_cnt, 1u);
        if (old == gridDim.x - 1u){
            g_bar_cnt = 0u;
            __threadfence();
            g_bar_gen = gen + 1u;
        } else {
            while (g_bar_gen == gen) __nanosleep(20);
        }
        __threadfence();
    }
    __syncthreads();
}
__device__ __forceinline__ void wait_ge(unsigned* ctr, unsigned target){
    __syncthreads();
    if (threadIdx.x == 0){
        volatile unsigned* p = (volatile unsigned*)ctr;
        unsigned v = *p;
        while ((int)(v - target) < 0){ __nanosleep(8); v = *p; }
        __threadfence();
    }
    __syncthreads();
}
__device__ __forceinline__ void signal_inc(unsigned* ctr){
    __syncthreads();
    if (threadIdx.x == 0){ __threadfence(); atomicAdd(ctr, 1u); }
}

// ---------------- megakernel ----------------
__global__ void __launch_bounds__(NTH,1) k_mega(
    const float* __restrict__ x,
    const float* __restrict__ conv_re_w, const float* __restrict__ conv_re_b,
    const float* __restrict__ conv_im_w, const float* __restrict__ conv_im_b,
    const float* __restrict__ pos,
    const float* __restrict__ bn_gamma, const float* __restrict__ bn_beta,
    const float* __restrict__ rms_w,
    const float* __restrict__ in_proj_w,
    const float* __restrict__ conv1d_w, const float* __restrict__ conv1d_b,
    const float* __restrict__ x_proj_w,
    const float* __restrict__ dt_proj_w, const float* __restrict__ dt_proj_b,
    const float* __restrict__ A_log,  const float* __restrict__ Dp,
    const float* __restrict__ out_proj_w,
    const float* __restrict__ fc_w, const float* __restrict__ fc_b,
    float* __restrict__ out)
{
    extern __shared__ float sm[];
    float* sxc  = sm + S_XC;
    float* sdl  = sm + S_DL;
    float* sdb  = sm + S_DB;
    float* stmp = sm + S_TMP;
    const int NB  = gridDim.x;
    const int bid = blockIdx.x;
    const int tid = threadIdx.x;
    const int gsz = NB*NTH;
    const int gtid = bid*NTH + tid;
    const int warp = tid >> 5, lane = tid & 31;

    const int seg_b = bid >> 2;
    const int seg_s = bid & 3;
    const int rowbase = bid*SEGL;

    // ===== phase 0 =====
    if (tid == 0){
        g_xz_ready[bid]=0u; g_xz_ack[bid]=0u;
        g_pq_ready[bid]=0u; g_pq_ack[bid]=0u;
    }
    for (int i = gtid; i < NL*ED*NS; i += gsz) g_A2[i] = -expf(A_log[i]) * L2E;
    for (int i = gtid; i < NL*ED; i += gsz){
        int layer = i / ED, e = i % ED;
        const float* wp = conv1d_w + i*3;
        float* dst = g_cwT + layer*4*ED;
        dst[0*ED+e] = wp[0];
        dst[1*ED+e] = wp[1];
        dst[2*ED+e] = wp[2];
        dst[3*ED+e] = conv1d_b[i];
    }
    if (gtid < 2*DM) g_bns[gtid] = 0.f;
    for (int idx = gtid; idx < ROWS*DM; idx += gsz){
        int row = idx / DM, o = idx % DM;
        int b = row / LP, l = row % LP;
        const float* xr = x + b*(2*LP*PP) + l*PP;
        const float* xi = xr + LP*PP;
        float acc;
        if (o < 6){
            acc = conv_re_b[o] - conv_im_b[o];
            const float* w1 = conv_re_w + o*PP; const float* w2 = conv_im_w + o*PP;
            #pragma unroll 10
            for (int k=0;k<PP;k++) acc += xr[k]*w1[k] - xi[k]*w2[k];
        } else {
            int o6 = o-6;
            acc = conv_re_b[o6] + conv_im_b[o6];
            const float* w1 = conv_re_w + o6*PP; const float* w2 = conv_im_w + o6*PP;
            #pragma unroll 10
            for (int k=0;k<PP;k++) acc += xi[k]*w1[k] + xr[k]*w2[k];
        }
        g_h[idx] = acc + pos[l*DM + o];
    }
    gridbar();

    // ===== BN sums =====
    {
        float ls[DM], lq[DM];
        #pragma unroll
        for(int c=0;c<DM;c++){ ls[c]=0.f; lq[c]=0.f; }
        for (int j = gtid; j < ROWS; j += gsz){
            #pragma unroll
            for(int c=0;c<DM;c++){ float v=g_h[j*DM+c]; ls[c]+=v; lq[c]+=v*v; }
        }
        #pragma unroll
        for(int c=0;c<DM;c++){
            float a=ls[c], q=lq[c];
            for(int off=16;off>0;off>>=1){
                a+=__shfl_down_sync(0xffffffffu,a,off);
                q+=__shfl_down_sync(0xffffffffu,q,off);
            }
            if (lane==0 && (a!=0.f || q!=0.f)){
                atomicAdd(&g_bns[c], a);
                atomicAdd(&g_bns[DM+c], q);
            }
        }
    }
    gridbar();

    // ===== BN apply + silu =====
    {
        if (tid < DM){
            float mu  = g_bns[tid]*(1.0f/ROWS);
            float var = g_bns[DM+tid]*(1.0f/ROWS) - mu*mu;
            float sc  = rsqrtf(var+1e-6f)*bn_gamma[tid];
            sm[tid]    = sc;
            sm[DM+tid] = bn_beta[tid] - mu*sc;
        }
        __syncthreads();
        for (int idx = gtid; idx < ROWS*DM; idx += gsz){
            int c = idx % DM;
            float v = g_h[idx]*sm[c] + sm[DM+c];
            g_h[idx] = siluf_(v);
        }
        __syncthreads();
    }
    gridbar();

    // ===== layers (pipelined; no grid barriers) =====
    for (int layer = 0; layer < NL; layer++){
        // ---- inproj: wait until downstream consumer released our xz rows ----
        if (layer >= 1 && seg_s < 3) wait_ge(&g_xz_ack[bid+1], (unsigned)layer);
        {
            float* su   = sxc;
            float* srms = sxc + 320;
            const float* Wl  = in_proj_w + layer*XZW*DM;
            const float* rwl = rms_w + layer*DM;
            if (tid < SEGL*DM) su[tid] = g_h[rowbase*DM + tid];
            __syncthreads();
            if (tid < SEGL){
                float s=0.f;
                #pragma unroll
                for(int d=0;d<DM;d++){ float v=su[tid*DM+d]; s+=v*v; }
                srms[tid] = rsqrtf(s*(1.0f/DM)+1e-5f);
            }
            __syncthreads();
            float uv = 0.f;
            if (tid < SEGL*DM) uv = su[tid]*srms[tid/DM]*rwl[tid%DM];
            __syncthreads();
            if (tid < SEGL*DM) su[tid] = uv;
            __syncthreads();
            float w[2][DM];
            #pragma unroll
            for(int j=0;j<2;j++){
                const float* wp = Wl + (tid + NTH*j)*DM;
                #pragma unroll
                for(int d=0;d<DM;d++) w[j][d]=wp[d];
            }
            for (int r=0;r<SEGL;r++){
                float u[DM];
                #pragma unroll
                for(int d=0;d<DM;d++) u[d]=su[r*DM+d];
                #pragma unroll
                for(int j=0;j<2;j++){
                    float acc=0.f;
                    #pragma unroll
                    for(int d=0;d<DM;d++) acc += u[d]*w[j][d];
                    g_xz[(rowbase+r)*XZW + tid + NTH*j] = acc;
                }
            }
        }
        signal_inc(&g_xz_ready[bid]);         // = layer+1

        // ---- cvxp: needs halo rows from bid-1 ----
        if (seg_s > 0) wait_ge(&g_xz_ready[bid-1], (unsigned)(layer+1));
        {
            const int pair  = warp >> 1;
            const int split = warp & 1;
            const int r0    = pair*2;
            const int grow0 = rowbase + r0;
            const int l0    = grow0 % LP;
            const float* cwT = g_cwT + layer*4*ED;
            const float* Wx  = x_proj_w + layer*DBLW*ED;
            float part[2][DBLW];
            #pragma unroll
            for(int r=0;r<2;r++)
                #pragma unroll
                for(int t=0;t<DBLW;t++) part[r][t]=0.f;
            #pragma unroll
            for (int c=0;c<3;c++){
                int e0 = split*384 + c*128 + lane*4;
                float4 w0 = __ldg((const float4*)(cwT + 0*ED + e0));
                float4 w1 = __ldg((const float4*)(cwT + 1*ED + e0));
                float4 w2 = __ldg((const float4*)(cwT + 2*ED + e0));
                float4 b4 = __ldg((const float4*)(cwT + 3*ED + e0));
                float4 xm2 = {0,0,0,0}, xm1 = {0,0,0,0};
                if (l0>=2) xm2 = *(const float4*)(g_xz + (grow0-2)*XZW + e0);
                if (l0>=1) xm1 = *(const float4*)(g_xz + (grow0-1)*XZW + e0);
                float4 x0 = *(const float4*)(g_xz + grow0*XZW + e0);
                float4 x1 = *(const float4*)(g_xz + (grow0+1)*XZW + e0);
                float4 xc0, xc1;
                xc0.x = siluf_(b4.x + w0.x*xm2.x + w1.x*xm1.x + w2.x*x0.x);
                xc0.y = siluf_(b4.y + w0.y*xm2.y + w1.y*xm1.y + w2.y*x0.y);
                xc0.z = siluf_(b4.z + w0.z*xm2.z + w1.z*xm1.z + w2.z*x0.z);
                xc0.w = siluf_(b4.w + w0.w*xm2.w + w1.w*xm1.w + w2.w*x0.w);
                xc1.x = siluf_(b4.x + w0.x*xm1.x + w1.x*x0.x + w2.x*x1.x);
                xc1.y = siluf_(b4.y + w0.y*xm1.y + w1.y*x0.y + w2.y*x1.y);
                xc1.z = siluf_(b4.z + w0.z*xm1.z + w1.z*x0.z + w2.z*x1.z);
                xc1.w = siluf_(b4.w + w0.w*xm1.w + w1.w*x0.w + w2.w*x1.w);
                *(float4*)(sxc + r0*ED + e0)     = xc0;
                *(float4*)(sxc + (r0+1)*ED + e0) = xc1;
                #pragma unroll
                for(int t=0;t<DBLW;t++){
                    float4 wt = __ldg((const float4*)(Wx + t*ED + e0));
                    part[0][t] += wt.x*xc0.x + wt.y*xc0.y + wt.z*xc0.z + wt.w*xc0.w;
                    part[1][t] += wt.x*xc1.x + wt.y*xc1.y + wt.z*xc1.z + wt.w*xc1.w;
                }
            }
            #pragma unroll
            for(int r=0;r<2;r++)
                #pragma unroll
                for(int t=0;t<DBLW;t++){
                    float v = part[r][t];
                    for(int off=16;off>0;off>>=1) v += __shfl_down_sync(0xffffffffu, v, off);
                    if (lane==0) stmp[(split*SEGL + r0 + r)*DBLW + t] = v;
                }
        }
        __syncthreads();
        if (tid == 0){ __threadfence(); atomicAdd(&g_xz_ack[bid], 1u); }  // halo reads done
        for (int idx = tid; idx < SEGL*DBLW; idx += NTH){
            int row = idx / DBLW, t = idx % DBLW;
            float v = stmp[row*DBLW + t] + stmp[(SEGL+row)*DBLW + t];
            sdb[row*DBLS + (t==0 ? 16 : (t-1))] = v;
        }
        __syncthreads();
        {
            float dw = dt_proj_w[layer*ED + tid];
            float db = dt_proj_b[layer*ED + tid];
            #pragma unroll 4
            for (int r=0;r<SEGL;r++){
                float d0 = sdb[r*DBLS + 16];
                sdl[r*ED + tid] = softplusf_(d0*dw + db);
            }
        }
        __syncthreads();

        // ---- local scan (h0 = 0): y_local into sxc; (P,q) for segs<3 ----
        int e = tid;
        float a2[NS];
        {
            const float* ap = g_A2 + (layer*ED + e)*NS;
            #pragma unroll
            for(int n=0;n<NS;n++) a2[n]=ap[n];
        }
        bool geo = true;
        #pragma unroll
        for(int n=1;n<NS;n++)
            geo = geo && (fabsf(a2[n] - (float)(n+1)*a2[0]) <= 1e-4f*fabsf(a2[n]));
        {
            float Dv = Dp[layer*ED + e];
            float st[NS], sumd = 0.f;
            #pragma unroll
            for(int n=0;n<NS;n++) st[n]=0.f;
            float z_n = g_xz[rowbase*XZW + ED + e];
            for (int li=0; li<SEGL; li++){
                float z = z_n;
                if (li < SEGL-1) z_n = g_xz[(rowbase+li+1)*XZW + ED + e];
                float delta = sdl[li*ED + e];
                float xc    = sxc[li*ED + e];
                float dx = delta * xc;
                float4 B0 = *(const float4*)(sdb + li*DBLS);
                float4 B1 = *(const float4*)(sdb + li*DBLS + 4);
                float4 C0 = *(const float4*)(sdb + li*DBLS + 8);
                float4 C1 = *(const float4*)(sdb + li*DBLS + 12);
                float Bv[NS] = {B0.x,B0.y,B0.z,B0.w,B1.x,B1.y,B1.z,B1.w};
                float Cv[NS] = {C0.x,C0.y,C0.z,C0.w,C1.x,C1.y,C1.z,C1.w};
                float y = Dv * xc;
                float p = ex2f_(delta * a2[0]);
                float dan = 1.f;
                #pragma unroll
                for(int n=0;n<NS;n++){
                    if (geo) dan *= p;
                    else     dan = ex2f_(delta * a2[n]);
                    st[n] = dan*st[n] + dx*Bv[n];
                    y += st[n]*Cv[n];
                }
                sumd += delta;
                // seg 0: y is final -> gate now; others: store raw y_local
                sxc[li*ED + e] = (seg_s == 0) ? (y * siluf_(z)) : y;
            }
            if (seg_s < 3){
                if (layer >= 2) wait_ge(&g_pq_ack[bid], (unsigned)((3-seg_s)*(layer-1)));
                int base = (layer&1)*PQSTRIDE + ((seg_s*BSZ + seg_b)*NS)*ED + e;
                #pragma unroll
                for(int n=0;n<NS;n++){
                    g_P[base + n*ED] = ex2f_(a2[n]*sumd);
                    g_q[base + n*ED] = st[n];
                }
                signal_inc(&g_pq_ready[bid]);   // = layer+1
            }
        }

        // ---- correction: add C * cumprod(da) * h_in, then gate ----
        if (seg_s > 0){
            for (int sp = 0; sp < seg_s; sp++)
                wait_ge(&g_pq_ready[(seg_b<<2)|sp], (unsigned)(layer+1));
            float hin[NS];
            #pragma unroll
            for(int n=0;n<NS;n++) hin[n]=0.f;
            for (int sp = 0; sp < seg_s; sp++){
                int base = (layer&1)*PQSTRIDE + ((sp*BSZ + seg_b)*NS)*ED + e;
                #pragma unroll
                for(int n=0;n<NS;n++)
                    hin[n] = g_P[base + n*ED]*hin[n] + g_q[base + n*ED];
            }
            float z_n = g_xz[rowbase*XZW + ED + e];
            if (geo){
                float cp = 1.f;
                for (int li=0; li<SEGL; li++){
                    float z = z_n;
                    if (li < SEGL-1) z_n = g_xz[(rowbase+li+1)*XZW + ED + e];
                    float delta = sdl[li*ED + e];
                    cp *= ex2f_(delta * a2[0]);
                    float4 C0 = *(const float4*)(sdb + li*DBLS + 8);
                    float4 C1 = *(const float4*)(sdb + li*DBLS + 12);
                    float Cv[NS] = {C0.x,C0.y,C0.z,C0.w,C1.x,C1.y,C1.z,C1.w};
                    float acc = 0.f;
                    #pragma unroll
                    for(int n=NS-1;n>=0;n--) acc = hin[n]*Cv[n] + cp*acc;
                    float y = sxc[li*ED + e] + cp*acc;
                    sxc[li*ED + e] = y * siluf_(z);
                }
            } else {
                float hc[NS];
                #pragma unroll
                for(int n=0;n<NS;n++) hc[n]=hin[n];
                for (int li=0; li<SEGL; li++){
                    float z = z_n;
                    if (li < SEGL-1) z_n = g_xz[(rowbase+li+1)*XZW + ED + e];
                    float delta = sdl[li*ED + e];
                    float4 C0 = *(const float4*)(sdb + li*DBLS + 8);
                    float4 C1 = *(const float4*)(sdb + li*DBLS + 12);
                    float Cv[NS] = {C0.x,C0.y,C0.z,C0.w,C1.x,C1.y,C1.z,C1.w};
                    float y = sxc[li*ED + e];
                    #pragma unroll
                    for(int n=0;n<NS;n++){
                        hc[n] *= ex2f_(delta * a2[n]);
                        y += hc[n]*Cv[n];
                    }
                    sxc[li*ED + e] = y * siluf_(z);
                }
            }
            __syncthreads();
            if (tid == 0){
                __threadfence();
                for (int sp = 0; sp < seg_s; sp++)
                    atomicAdd(&g_pq_ack[(seg_b<<2)|sp], 1u);
            }
        }
        __syncthreads();

        // ---- out_proj ----
        {
            const int pair  = warp >> 1;
            const int split = warp & 1;
            const int r0    = pair*2;
            const float* Wo = out_proj_w + layer*DM*ED;
            float pd[2][DM];
            #pragma unroll
            for(int r=0;r<2;r++)
                #pragma unroll
                for(int d=0;d<DM;d++) pd[r][d]=0.f;
            #pragma unroll
            for (int c=0;c<3;c++){
                int e0 = split*384 + c*128 + lane*4;
                float4 y0 = *(const float4*)(sxc + r0*ED + e0);
                float4 y1 = *(const float4*)(sxc + (r0+1)*ED + e0);
                #pragma unroll
                for(int d=0;d<DM;d++){
                    float4 wd4 = __ldg((const float4*)(Wo + d*ED + e0));
                    pd[0][d] += wd4.x*y0.x + wd4.y*y0.y + wd4.z*y0.z + wd4.w*y0.w;
                    pd[1][d] += wd4.x*y1.x + wd4.y*y1.y + wd4.z*y1.z + wd4.w*y1.w;
                }
            }
            #pragma unroll
            for(int r=0;r<2;r++)
                #pragma unroll
                for(int d=0;d<DM;d++){
                    float v = pd[r][d];
                    for(int off=16;off>0;off>>=1) v += __shfl_down_sync(0xffffffffu, v, off);
                    if (lane==0) stmp[(split*SEGL + r0 + r)*DM + d] = v;
                }
        }
        __syncthreads();
        for (int idx = tid; idx < SEGL*DM; idx += NTH){
            int row = idx / DM, d = idx % DM;
            g_h[(rowbase+row)*DM + d] += stmp[row*DM + d] + stmp[(SEGL+row)*DM + d];
        }
        __syncthreads();
    }
    gridbar();

    // ===== final: mean over L + FC + ReLU =====
    {
        float* m = sm;
        for (int b = bid; b < BSZ; b += NB){
            if (tid < DM){
                float s=0.f;
                for(int l=0;l<LP;l++) s += g_h[(b*LP+l)*DM + tid];
                m[tid]=s*(1.0f/LP);
            }
            __syncthreads();
            if (tid < EMB){
                float acc = fc_b[tid];
                #pragma unroll
                for(int d=0;d<DM;d++) acc += m[d]*fc_w[tid*DM+d];
                out[b*EMB+tid] = fmaxf(acc,0.0f);
            }
            __syncthreads();
        }
    }
}

// ---------------- launch ----------------
extern "C" void kernel_launch(void* const* d_in, const int* in_sizes, int n_in,
                              void* d_out, int out_size){
    const float* x          = (const float*)d_in[0];
    const float* conv_re_w  = (const float*)d_in[1];
    const float* conv_re_b  = (const float*)d_in[2];
    const float* conv_im_w  = (const float*)d_in[3];
    const float* conv_im_b  = (const float*)d_in[4];
    const float* pos        = (const float*)d_in[5];
    const float* bn_gamma   = (const float*)d_in[6];
    const float* bn_beta    = (const float*)d_in[7];
    const float* rms_w      = (const float*)d_in[8];
    const float* in_proj_w  = (const float*)d_in[9];
    const float* conv1d_w   = (const float*)d_in[10];
    const float* conv1d_b   = (const float*)d_in[11];
    const float* x_proj_w   = (const float*)d_in[12];
    const float* dt_proj_w  = (const float*)d_in[13];
    const float* dt_proj_b  = (const float*)d_in[14];
    const float* A_log      = (const float*)d_in[15];
    const float* Dp         = (const float*)d_in[16];
    const float* out_proj_w = (const float*)d_in[17];
    const float* fc_w       = (const float*)d_in[18];
    const float* fc_b       = (const float*)d_in[19];
    float* out = (float*)d_out;

    size_t dynbytes = (size_t)DYNF * sizeof(float);
    cudaFuncSetAttribute(k_mega, cudaFuncAttributeMaxDynamicSharedMemorySize, (int)dynbytes);

    k_mega<<<NBLK, NTH, dynbytes>>>(x, conv_re_w, conv_re_b, conv_im_w, conv_im_b, pos,
                         bn_gamma, bn_beta, rms_w, in_proj_w, conv1d_w, conv1d_b,
                         x_proj_w, dt_proj_w, dt_proj_b, A_log, Dp, out_proj_w,
                         fc_w, fc_b, out);
}